// round 12
// baseline (speedup 1.0000x reference)
#include <cuda_runtime.h>
#include <cuda_fp16.h>
#include <math.h>
#include <stdint.h>

// ---------------------------------------------------------------------------
// GraphTransformer layer: N=50000, E=600000, C=128, H=8, Dh=16
// Round 12: e2/h2 carried as half between Wo and FFN2 (residual round-trip
// halved); dist computed in ep-GEMM epilogue (post-mainloop, pipeline intact).
// ---------------------------------------------------------------------------

#define N_MAX 50000
#define E_MAX 600000

__device__ __half g_hln[(size_t)N_MAX * 128];   // ln1n / h_attn / ln2n (half)
__device__ __half g_qkv[(size_t)N_MAX * 384];   // q|k|v, then h2 (half)
__device__ __half g_eln[(size_t)E_MAX * 128];   // ln1e / alpha / ln2e (half)
__device__ __half g_ep [(size_t)E_MAX * 128];   // ep, then e2 (half)
__device__ float  g_wV [(size_t)N_MAX * 128];
__device__ float  g_z  [(size_t)N_MAX * 8];
__device__ __half g_t  [(size_t)E_MAX * 256];   // FFN hidden (half)
__device__ __half g_wT [229376];                // transposed half weights
__device__ int    g_is64;

// ---------------------------------------------------------------------------
// MMA + cp.async primitives
// ---------------------------------------------------------------------------
__device__ __forceinline__ void mma_f16(float* c, const uint32_t* a,
                                        uint32_t b0, uint32_t b1) {
    asm volatile(
        "mma.sync.aligned.m16n8k16.row.col.f32.f16.f16.f32 "
        "{%0,%1,%2,%3}, {%4,%5,%6,%7}, {%8,%9}, {%0,%1,%2,%3};"
        : "+f"(c[0]), "+f"(c[1]), "+f"(c[2]), "+f"(c[3])
        : "r"(a[0]), "r"(a[1]), "r"(a[2]), "r"(a[3]), "r"(b0), "r"(b1));
}
#define CP16(d, s, n) asm volatile("cp.async.cg.shared.global [%0], [%1], 16, %2;" :: "r"(d), "l"(s), "r"(n) : "memory")
#define CPCOMMIT()    asm volatile("cp.async.commit_group;" ::: "memory")
#define CPWAIT(n)     asm volatile("cp.async.wait_group %0;" :: "n"(n) : "memory")

#define SKH 40
#define CHUNKH (128 * SKH)
#define CHUNKB (CHUNKH * 2)
#define NSTAGE 3
#define GEMM_DYN_SMEM (2 * NSTAGE * CHUNKB)   // 61440 B

__device__ __forceinline__ int edge_idx(const void* __restrict__ ei, long long pos)
{
    if (g_is64) return (int)((const long long*)ei)[pos];
    return ((const int*)ei)[pos];
}

// ---------------------------------------------------------------------------
// 256-thread fp16 HMMA GEMM (tile 128x128, BK=32, 4x2 warps, 3-stage pipe)
// Plain epilogue: +bias, +dist(coords/eidx)*r1n, SiLU, +resid(fp32|half);
// write fp32 (Cf) or half (Ch).
// LN epilogue (lng!=null): bias+resid(fp32) -> half Ch AND LayerNorm -> lnout.
// ---------------------------------------------------------------------------
__global__ void __launch_bounds__(256, 2) mma_gemm(
    const __half* __restrict__ Ah, int lda,
    const __half* __restrict__ BT,
    float* __restrict__ Cf, __half* __restrict__ Ch,
    int M, int K, int ldc,
    const float* __restrict__ bias,
    const float* __restrict__ resid, const __half* __restrict__ residh, int ldr,
    const float* __restrict__ r1n,
    const float* __restrict__ coords, const void* __restrict__ eidx, long long Etot,
    int act,
    const float* __restrict__ lng, const float* __restrict__ lnb,
    __half* __restrict__ lnout)
{
    extern __shared__ __half dyn[];
    __half* sA = dyn;
    __half* sB = dyn + NSTAGE * CHUNKH;
    __shared__ float red[128][2][2];
    __shared__ float sDist[128];

    const int tid = threadIdx.x;
    const int wid = tid >> 5;
    const int lane = tid & 31;
    const int warp_m = wid & 3;
    const int warp_n = wid >> 2;
    const int m0 = blockIdx.x * 128;
    const int n0 = blockIdx.y * 128;
    const int grp = lane >> 2;
    const int tig = lane & 3;

    const uint32_t sA0 = (uint32_t)__cvta_generic_to_shared(sA);
    const uint32_t sB0 = (uint32_t)__cvta_generic_to_shared(sB);
    const int arow = tid >> 2, aj = tid & 3;

    float acc[2][8][4];
    #pragma unroll
    for (int t = 0; t < 2; t++)
        #pragma unroll
        for (int j = 0; j < 8; j++)
            #pragma unroll
            for (int c = 0; c < 4; c++) acc[t][j][c] = 0.0f;

    const int nc = K >> 5;

    auto loadB = [&](int c, int buf) {
        const int k0 = c << 5;
        #pragma unroll
        for (int i = 0; i < 2; i++) {
            const int row = arow + i * 64;
            const uint32_t dst = sB0 + buf * CHUNKB + row * (SKH * 2) + aj * 16;
            const __half* src = BT + (size_t)(n0 + row) * K + k0 + aj * 8;
            CP16(dst, src, 16);
        }
    };
    auto loadA = [&](int c, int buf) {
        const int k0 = c << 5;
        #pragma unroll
        for (int i = 0; i < 2; i++) {
            const int row = arow + i * 64;
            const uint32_t dst = sA0 + buf * CHUNKB + row * (SKH * 2) + aj * 16;
            const int ok = (m0 + row) < M;
            const __half* src = Ah + (size_t)(ok ? (m0 + row) : 0) * lda + k0 + aj * 8;
            CP16(dst, src, ok ? 16 : 0);
        }
    };
    auto compute = [&](int buf) {
        const __half* Ab = sA + buf * CHUNKH;
        const __half* Bb = sB + buf * CHUNKH;
        #pragma unroll
        for (int ks = 0; ks < 2; ks++) {
            const int kk = ks * 16;
            uint32_t a[2][4];
            #pragma unroll
            for (int t = 0; t < 2; t++) {
                const __half* ap = Ab + (warp_m * 32 + t * 16 + grp) * SKH + kk + 2 * tig;
                a[t][0] = *(const uint32_t*)(ap);
                a[t][1] = *(const uint32_t*)(ap + 8 * SKH);
                a[t][2] = *(const uint32_t*)(ap + 8);
                a[t][3] = *(const uint32_t*)(ap + 8 * SKH + 8);
            }
            #pragma unroll
            for (int j = 0; j < 8; j++) {
                const __half* bp = Bb + (warp_n * 64 + j * 8 + grp) * SKH + kk + 2 * tig;
                const uint32_t b0 = *(const uint32_t*)(bp);
                const uint32_t b1 = *(const uint32_t*)(bp + 8);
                mma_f16(acc[0][j], a[0], b0, b1);
                mma_f16(acc[1][j], a[1], b0, b1);
            }
        }
    };

    loadA(0, 0); loadB(0, 0); CPCOMMIT();
    if (nc > 1) { loadA(1, 1); loadB(1, 1); }
    CPCOMMIT();
    int buf = 0;
    for (int c = 0; c < nc; c++) {
        if (c + 2 < nc) {
            int b2 = buf + 2; if (b2 >= NSTAGE) b2 -= NSTAGE;
            loadA(c + 2, b2); loadB(c + 2, b2);
        }
        CPCOMMIT();
        CPWAIT(2);
        __syncthreads();
        compute(buf);
        __syncthreads();
        if (++buf == NSTAGE) buf = 0;
    }

    // per-row edge distance (post-mainloop; does not touch the pipeline)
    if (coords) {
        if (tid < 128) {
            const int m = m0 + tid;
            const int e = (m < M) ? m : 0;
            const int rr = edge_idx(eidx, e);
            const int cc = edge_idx(eidx, Etot + e);
            const float dx = coords[rr * 3 + 0] - coords[cc * 3 + 0];
            const float dy = coords[rr * 3 + 1] - coords[cc * 3 + 1];
            const float dz = coords[rr * 3 + 2] - coords[cc * 3 + 2];
            sDist[tid] = 0.1f * sqrtf(dx * dx + dy * dy + dz * dz);
        }
        __syncthreads();
    }

    if (lng == nullptr) {
        #pragma unroll
        for (int t = 0; t < 2; t++) {
            #pragma unroll
            for (int hh = 0; hh < 2; hh++) {
                const int rl = warp_m * 32 + t * 16 + grp + hh * 8;
                const int m = m0 + rl;
                if (m >= M) continue;
                const float r1 = coords ? sDist[rl] : 0.0f;
                const float* rrow = resid ? resid + (size_t)m * ldr : nullptr;
                const __half* hrow = residh ? residh + (size_t)m * ldr : nullptr;
                #pragma unroll
                for (int j = 0; j < 8; j++) {
                    const int col = n0 + warp_n * 64 + j * 8 + tig * 2;
                    float v0 = acc[t][j][hh * 2 + 0];
                    float v1 = acc[t][j][hh * 2 + 1];
                    if (bias) { v0 += bias[col]; v1 += bias[col + 1]; }
                    if (r1n)  { v0 += r1 * r1n[col]; v1 += r1 * r1n[col + 1]; }
                    if (act) {
                        v0 = v0 / (1.0f + __expf(-v0));
                        v1 = v1 / (1.0f + __expf(-v1));
                    }
                    if (resid) { v0 += rrow[col]; v1 += rrow[col + 1]; }
                    if (residh) {
                        const float2 h2 = __half22float2(*(const __half2*)(hrow + col));
                        v0 += h2.x; v1 += h2.y;
                    }
                    if (Ch) {
                        *(__half2*)(Ch + (size_t)m * ldc + col) = __floats2half2_rn(v0, v1);
                    } else {
                        float2 o2; o2.x = v0; o2.y = v1;
                        *(float2*)(Cf + (size_t)m * ldc + col) = o2;
                    }
                }
            }
        }
    } else {
        // fused bias+resid(fp32) -> Ch (half), then LayerNorm -> lnout (half)
        float s[2][2], sq[2][2];
        #pragma unroll
        for (int t = 0; t < 2; t++) {
            #pragma unroll
            for (int hh = 0; hh < 2; hh++) {
                const int m = m0 + warp_m * 32 + t * 16 + grp + hh * 8;
                const bool ok = m < M;
                const float* rrow = ok ? resid + (size_t)m * ldr : nullptr;
                float sum = 0.f, sumsq = 0.f;
                #pragma unroll
                for (int j = 0; j < 8; j++) {
                    const int col = warp_n * 64 + j * 8 + tig * 2;
                    float v0 = acc[t][j][hh * 2 + 0] + bias[col];
                    float v1 = acc[t][j][hh * 2 + 1] + bias[col + 1];
                    if (ok) { v0 += rrow[col]; v1 += rrow[col + 1]; }
                    acc[t][j][hh * 2 + 0] = v0;
                    acc[t][j][hh * 2 + 1] = v1;
                    if (ok)
                        *(__half2*)(Ch + (size_t)m * ldc + col) = __floats2half2_rn(v0, v1);
                    sum += v0 + v1;
                    sumsq += v0 * v0 + v1 * v1;
                }
                s[t][hh] = sum; sq[t][hh] = sumsq;
            }
        }
        #pragma unroll
        for (int t = 0; t < 2; t++)
            #pragma unroll
            for (int hh = 0; hh < 2; hh++) {
                s[t][hh]  += __shfl_xor_sync(0xffffffffu, s[t][hh], 1);
                s[t][hh]  += __shfl_xor_sync(0xffffffffu, s[t][hh], 2);
                sq[t][hh] += __shfl_xor_sync(0xffffffffu, sq[t][hh], 1);
                sq[t][hh] += __shfl_xor_sync(0xffffffffu, sq[t][hh], 2);
            }
        if (tig == 0) {
            #pragma unroll
            for (int t = 0; t < 2; t++)
                #pragma unroll
                for (int hh = 0; hh < 2; hh++) {
                    const int row = warp_m * 32 + t * 16 + hh * 8 + grp;
                    red[row][warp_n][0] = s[t][hh];
                    red[row][warp_n][1] = sq[t][hh];
                }
        }
        __syncthreads();
        #pragma unroll
        for (int t = 0; t < 2; t++) {
            #pragma unroll
            for (int hh = 0; hh < 2; hh++) {
                const int row = warp_m * 32 + t * 16 + hh * 8 + grp;
                const int m = m0 + row;
                if (m >= M) continue;
                const float S = red[row][0][0] + red[row][1][0];
                const float Q = red[row][0][1] + red[row][1][1];
                const float mu = S * (1.0f / 128.0f);
                const float var = Q * (1.0f / 128.0f) - mu * mu;
                const float rs = rsqrtf(var + 1e-5f);
                #pragma unroll
                for (int j = 0; j < 8; j++) {
                    const int col = warp_n * 64 + j * 8 + tig * 2;
                    float v0 = (acc[t][j][hh * 2 + 0] - mu) * rs * lng[col] + lnb[col];
                    float v1 = (acc[t][j][hh * 2 + 1] - mu) * rs * lng[col + 1] + lnb[col + 1];
                    *(__half2*)(lnout + (size_t)m * 128 + col) = __floats2half2_rn(v0, v1);
                }
            }
        }
    }
}

// ---------------------------------------------------------------------------
// Batched weight transpose to half
// ---------------------------------------------------------------------------
struct TransBatch {
    const float* src[10];
    __half* dst[10];
    int R[10], C[10];
};

__global__ void transpose_all(TransBatch tb)
{
    __shared__ float tile[32][33];
    const int i = blockIdx.z;
    const int R = tb.R[i], Cc = tb.C[i];
    const int c0 = blockIdx.x * 32, r0 = blockIdx.y * 32;
    if (c0 >= Cc || r0 >= R) return;
    const float* src = tb.src[i];
    __half* dst = tb.dst[i];
    int tx = threadIdx.x, ty = threadIdx.y;
    for (int dy = 0; dy < 32; dy += 8) {
        int r = r0 + ty + dy, c = c0 + tx;
        if (r < R && c < Cc) tile[ty + dy][tx] = src[(size_t)r * Cc + c];
    }
    __syncthreads();
    for (int dy = 0; dy < 32; dy += 8) {
        int c = c0 + ty + dy, r = r0 + tx;
        if (r < R && c < Cc) dst[(size_t)c * R + r] = __float2half_rn(tile[tx][ty + dy]);
    }
}

// ---------------------------------------------------------------------------
// misc kernels
// ---------------------------------------------------------------------------
__global__ void detect_kernel(const int* __restrict__ ei32)
{
    if (threadIdx.x == 0 && blockIdx.x == 0) {
        int any = 0;
        #pragma unroll 8
        for (int i = 0; i < 64; i++) any |= ei32[2 * i + 1];
        g_is64 = (any == 0) ? 1 : 0;
    }
}

// merged LayerNorm: rows [0,M1) from set 1, rows [M1,M1+M2) from set 2
__global__ void ln2_kernel(const float* __restrict__ x1,
                           const float* __restrict__ g1, const float* __restrict__ b1,
                           __half* __restrict__ o1, int M1,
                           const float* __restrict__ x2,
                           const float* __restrict__ g2, const float* __restrict__ b2,
                           __half* __restrict__ o2, int M2)
{
    int w = (blockIdx.x * blockDim.x + threadIdx.x) >> 5;
    int lane = threadIdx.x & 31;
    const float *x, *g, *b; __half* o; int row;
    if (w < M1) { x = x1; g = g1; b = b1; o = o1; row = w; }
    else if (w < M1 + M2) { x = x2; g = g2; b = b2; o = o2; row = w - M1; }
    else return;
    float4 v = *(const float4*)(x + (size_t)row * 128 + lane * 4);
    float s  = v.x + v.y + v.z + v.w;
    float sq = v.x*v.x + v.y*v.y + v.z*v.z + v.w*v.w;
    #pragma unroll
    for (int off = 16; off; off >>= 1) {
        s  += __shfl_xor_sync(0xffffffffu, s,  off);
        sq += __shfl_xor_sync(0xffffffffu, sq, off);
    }
    float mu  = s * (1.0f / 128.0f);
    float var = sq * (1.0f / 128.0f) - mu * mu;
    float rs  = rsqrtf(var + 1e-5f);
    float4 gv = *(const float4*)(g + lane * 4);
    float4 bv = *(const float4*)(b + lane * 4);
    __half2 h0 = __floats2half2_rn((v.x - mu) * rs * gv.x + bv.x,
                                   (v.y - mu) * rs * gv.y + bv.y);
    __half2 h1 = __floats2half2_rn((v.z - mu) * rs * gv.z + bv.z,
                                   (v.w - mu) * rs * gv.w + bv.w);
    uint2 u; u.x = *(uint32_t*)&h0; u.y = *(uint32_t*)&h1;
    *(uint2*)(o + (size_t)row * 128 + lane * 4) = u;
}

__global__ void fill0_2(float* __restrict__ p1, size_t n1,
                        float* __restrict__ p2, size_t n2)
{
    size_t i = (size_t)blockIdx.x * blockDim.x + threadIdx.x;
    if (i < n1) p1[i] = 0.0f;
    else if (i < n1 + n2) p2[i - n1] = 0.0f;
}

// edge attention: 8 lanes per edge (one head per lane, no shuffle),
// uint4 loads, vector red.global for segment sums.
__global__ void attn_edge_kernel(const __half* __restrict__ qkv,
                                 const __half* __restrict__ ep,
                                 __half* __restrict__ alpha_h,
                                 const void* __restrict__ ei,
                                 float* __restrict__ wV,
                                 float* __restrict__ z,
                                 int E)
{
    const int idx = blockIdx.x * blockDim.x + threadIdx.x;
    const int e = idx >> 3;
    const int l = threadIdx.x & 7;
    if (e >= E) return;
    const int r = edge_idx(ei, e);
    const int c = edge_idx(ei, (long long)E + e);

    const __half* qp  = qkv + (size_t)c * 384 + l * 16;
    const __half* kp  = qkv + (size_t)r * 384 + 128 + l * 16;
    const __half* vp  = qkv + (size_t)r * 384 + 256 + l * 16;
    const __half* epp = ep + (size_t)e * 128 + l * 16;

    const uint4 qu0 = *(const uint4*)(qp);
    const uint4 qu1 = *(const uint4*)(qp + 8);
    const uint4 ku0 = *(const uint4*)(kp);
    const uint4 ku1 = *(const uint4*)(kp + 8);
    const uint4 vu0 = *(const uint4*)(vp);
    const uint4 vu1 = *(const uint4*)(vp + 8);
    const uint4 eu0 = *(const uint4*)(epp);
    const uint4 eu1 = *(const uint4*)(epp + 8);

    float a[16], vv[16];
    float hs = 0.0f;
    #pragma unroll
    for (int i = 0; i < 8; i++) {
        const uint32_t qw = (i < 4) ? (&qu0.x)[i] : (&qu1.x)[i - 4];
        const uint32_t kw = (i < 4) ? (&ku0.x)[i] : (&ku1.x)[i - 4];
        const uint32_t vw = (i < 4) ? (&vu0.x)[i] : (&vu1.x)[i - 4];
        const uint32_t ew = (i < 4) ? (&eu0.x)[i] : (&eu1.x)[i - 4];
        const float2 qf = __half22float2(*(const __half2*)&qw);
        const float2 kf = __half22float2(*(const __half2*)&kw);
        const float2 vf = __half22float2(*(const __half2*)&vw);
        const float2 ef = __half22float2(*(const __half2*)&ew);
        float a0 = fminf(fmaxf(kf.x * qf.x * 0.25f, -5.0f), 5.0f) * ef.x;
        float a1 = fminf(fmaxf(kf.y * qf.y * 0.25f, -5.0f), 5.0f) * ef.y;
        a[i * 2 + 0] = a0; a[i * 2 + 1] = a1;
        vv[i * 2 + 0] = vf.x; vv[i * 2 + 1] = vf.y;
        hs += a0 + a1;
    }

    uint4 au0, au1;
    #pragma unroll
    for (int i = 0; i < 4; i++) {
        __half2 h0 = __floats2half2_rn(a[i * 2], a[i * 2 + 1]);
        __half2 h1 = __floats2half2_rn(a[8 + i * 2], a[8 + i * 2 + 1]);
        (&au0.x)[i] = *(uint32_t*)&h0;
        (&au1.x)[i] = *(uint32_t*)&h1;
    }
    *(uint4*)(alpha_h + (size_t)e * 128 + l * 16) = au0;
    *(uint4*)(alpha_h + (size_t)e * 128 + l * 16 + 8) = au1;

    const float ax = __expf(fminf(fmaxf(hs, -5.0f), 5.0f));

    float* wvp = wV + (size_t)c * 128 + l * 16;
    asm volatile("red.global.add.v4.f32 [%0], {%1, %2, %3, %4};"
                 :: "l"(wvp), "f"(vv[0] * ax), "f"(vv[1] * ax),
                    "f"(vv[2] * ax), "f"(vv[3] * ax) : "memory");
    asm volatile("red.global.add.v4.f32 [%0], {%1, %2, %3, %4};"
                 :: "l"(wvp + 4), "f"(vv[4] * ax), "f"(vv[5] * ax),
                    "f"(vv[6] * ax), "f"(vv[7] * ax) : "memory");
    asm volatile("red.global.add.v4.f32 [%0], {%1, %2, %3, %4};"
                 :: "l"(wvp + 8), "f"(vv[8] * ax), "f"(vv[9] * ax),
                    "f"(vv[10] * ax), "f"(vv[11] * ax) : "memory");
    asm volatile("red.global.add.v4.f32 [%0], {%1, %2, %3, %4};"
                 :: "l"(wvp + 12), "f"(vv[12] * ax), "f"(vv[13] * ax),
                    "f"(vv[14] * ax), "f"(vv[15] * ax) : "memory");
    asm volatile("red.global.add.f32 [%0], %1;"
                 :: "l"(z + (size_t)c * 8 + l), "f"(ax) : "memory");
}

__global__ void hattn_kernel(const float* __restrict__ wV,
                             const float* __restrict__ z,
                             __half* __restrict__ out, int N)
{
    int i = blockIdx.x * blockDim.x + threadIdx.x;
    if (i >= N * 128) return;
    int n = i >> 7;
    int h = (i & 127) >> 4;
    out[i] = __float2half_rn(wV[i] / (z[(size_t)n * 8 + h] + 1e-6f));
}

// ---------------------------------------------------------------------------
// Launch
// ---------------------------------------------------------------------------
extern "C" void kernel_launch(void* const* d_in, const int* in_sizes, int n_in,
                              void* d_out, int out_size)
{
    const float* node_feats = (const float*)d_in[0];
    const float* edge_feats = (const float*)d_in[1];
    const float* coords     = (const float*)d_in[2];
    const void*  ei         = d_in[3];
    const float* Wq   = (const float*)d_in[4];
    const float* Wk   = (const float*)d_in[5];
    const float* Wv   = (const float*)d_in[6];
    const float* We   = (const float*)d_in[7];
    const float* Wo_n = (const float*)d_in[8];
    const float* bo_n = (const float*)d_in[9];
    const float* Wo_e = (const float*)d_in[10];
    const float* bo_e = (const float*)d_in[11];
    const float* ln1n_g = (const float*)d_in[12];
    const float* ln1n_b = (const float*)d_in[13];
    const float* ln1e_g = (const float*)d_in[14];
    const float* ln1e_b = (const float*)d_in[15];
    const float* ln2n_g = (const float*)d_in[16];
    const float* ln2n_b = (const float*)d_in[17];
    const float* ln2e_g = (const float*)d_in[18];
    const float* ln2e_b = (const float*)d_in[19];
    const float* Wn1 = (const float*)d_in[20];
    const float* Wn2 = (const float*)d_in[21];
    const float* We1 = (const float*)d_in[22];
    const float* We2 = (const float*)d_in[23];

    int N = in_sizes[0] / 128;
    int E = in_sizes[1] / 128;

    float* out   = (float*)d_out;
    float* out_n = out;
    float* out_e = out + (size_t)N * 128;

    __half *p_hln, *p_qkv, *p_eln, *p_ep, *p_t, *p_wT;
    float *p_wV, *p_z;
    cudaGetSymbolAddress((void**)&p_hln,  g_hln);
    cudaGetSymbolAddress((void**)&p_qkv,  g_qkv);
    cudaGetSymbolAddress((void**)&p_eln,  g_eln);
    cudaGetSymbolAddress((void**)&p_ep,   g_ep);
    cudaGetSymbolAddress((void**)&p_wV,   g_wV);
    cudaGetSymbolAddress((void**)&p_z,    g_z);
    cudaGetSymbolAddress((void**)&p_t,    g_t);
    cudaGetSymbolAddress((void**)&p_wT,   g_wT);

    __half* WqkvT = p_wT + 0;        // [384,128]
    __half* WeT   = p_wT + 49152;    // [128,128]
    __half* WonT  = p_wT + 65536;
    __half* WoeT  = p_wT + 81920;
    __half* Wn1T  = p_wT + 98304;    // [256,128]
    __half* Wn2T  = p_wT + 131072;   // [128,256]
    __half* We1T  = p_wT + 163840;
    __half* We2T  = p_wT + 196608;

    dim3 blk(256);

    cudaFuncSetAttribute(mma_gemm, cudaFuncAttributeMaxDynamicSharedMemorySize,
                         GEMM_DYN_SMEM);

    detect_kernel<<<1, 32>>>((const int*)ei);

    {
        TransBatch tb;
        const float* srcs[10] = {Wq, Wk, Wv, We, Wo_n, Wo_e, Wn1, Wn2, We1, We2};
        __half* dsts[10] = {WqkvT, WqkvT + 16384, WqkvT + 32768, WeT, WonT, WoeT,
                            Wn1T, Wn2T, We1T, We2T};
        int Rs[10] = {128, 128, 128, 128, 128, 128, 128, 256, 128, 256};
        int Cs[10] = {128, 128, 128, 128, 128, 128, 256, 128, 256, 128};
        for (int i = 0; i < 10; i++) {
            tb.src[i] = srcs[i]; tb.dst[i] = dsts[i]; tb.R[i] = Rs[i]; tb.C[i] = Cs[i];
        }
        transpose_all<<<dim3(8, 8, 10), dim3(32, 8)>>>(tb);
    }

    ln2_kernel<<<(N + E + 7) / 8, blk>>>(node_feats, ln1n_g, ln1n_b, p_hln, N,
                                         edge_feats, ln1e_g, ln1e_b, p_eln, E);
    fill0_2<<<(int)(((size_t)N * 136 + 255) / 256), blk>>>(p_wV, (size_t)N * 128,
                                                           p_z, (size_t)N * 8);

    const int gN = (N + 127) / 128;
    const int gE = (E + 127) / 128;

    // qkv: [N,128]h @ [128,384] -> half
    mma_gemm<<<dim3(gN, 3), blk, GEMM_DYN_SMEM>>>(
        p_hln, 128, WqkvT, nullptr, p_qkv, N, 128, 384,
        nullptr, nullptr, nullptr, 0, nullptr,
        nullptr, nullptr, 0, 0, nullptr, nullptr, nullptr);

    // ep = LN(e) @ We[0:128] + dist (x) We[128]; dist computed in epilogue
    mma_gemm<<<dim3(gE, 1), blk, GEMM_DYN_SMEM>>>(
        p_eln, 128, WeT, nullptr, p_ep, E, 128, 128,
        nullptr, nullptr, nullptr, 0, We + 128 * 128,
        coords, ei, (long long)E, 0, nullptr, nullptr, nullptr);

    // attention: alpha (half) into p_eln; reductions into wV, z
    attn_edge_kernel<<<(E + 31) / 32, blk>>>(p_qkv, p_ep, p_eln, ei, p_wV, p_z, E);
    hattn_kernel<<<(N * 128 + 255) / 256, blk>>>(p_wV, p_z, p_hln, N);

    // h2 (half) -> p_qkv; LN2n -> p_hln
    mma_gemm<<<dim3(gN, 1), blk, GEMM_DYN_SMEM>>>(
        p_hln, 128, WonT, nullptr, p_qkv, N, 128, 128,
        bo_n, node_feats, nullptr, 128, nullptr,
        nullptr, nullptr, 0, 0, ln2n_g, ln2n_b, p_hln);
    // e2 (half) -> p_ep; LN2e -> p_eln
    mma_gemm<<<dim3(gE, 1), blk, GEMM_DYN_SMEM>>>(
        p_eln, 128, WoeT, nullptr, p_ep, E, 128, 128,
        bo_e, edge_feats, nullptr, 128, nullptr,
        nullptr, nullptr, 0, 0, ln2e_g, ln2e_b, p_eln);

    // node FFN: t = silu(ln2n @ Wn1); out_n = h2(half) + t @ Wn2
    mma_gemm<<<dim3(gN, 2), blk, GEMM_DYN_SMEM>>>(
        p_hln, 128, Wn1T, nullptr, p_t, N, 128, 256,
        nullptr, nullptr, nullptr, 0, nullptr,
        nullptr, nullptr, 0, 1, nullptr, nullptr, nullptr);
    mma_gemm<<<dim3(gN, 1), blk, GEMM_DYN_SMEM>>>(
        p_t, 256, Wn2T, out_n, nullptr, N, 256, 128,
        nullptr, nullptr, p_qkv, 128, nullptr,
        nullptr, nullptr, 0, 0, nullptr, nullptr, nullptr);

    // edge FFN: t = silu(ln2e @ We1); out_e = e2(half) + t @ We2
    mma_gemm<<<dim3(gE, 2), blk, GEMM_DYN_SMEM>>>(
        p_eln, 128, We1T, nullptr, p_t, E, 128, 256,
        nullptr, nullptr, nullptr, 0, nullptr,
        nullptr, nullptr, 0, 1, nullptr, nullptr, nullptr);
    mma_gemm<<<dim3(gE, 1), blk, GEMM_DYN_SMEM>>>(
        p_t, 256, We2T, out_e, nullptr, E, 256, 128,
        nullptr, nullptr, p_ep, 128, nullptr,
        nullptr, nullptr, 0, 0, nullptr, nullptr, nullptr);
}

// round 13
// speedup vs baseline: 1.0500x; 1.0500x over previous
#include <cuda_runtime.h>
#include <cuda_fp16.h>
#include <math.h>
#include <stdint.h>

// ---------------------------------------------------------------------------
// GraphTransformer layer: N=50000, E=600000, C=128, H=8, Dh=16
// Round 13: round-10 champion structure (static 2-stage GEMM, 16-lane attn,
// fp32 residuals) + merged LN1 launch + cudaMemsetAsync fills.
// ---------------------------------------------------------------------------

#define N_MAX 50000
#define E_MAX 600000

__device__ __half g_hln[(size_t)N_MAX * 128];   // ln1n / h_attn / ln2n (half)
__device__ __half g_qkv[(size_t)N_MAX * 384];   // q|k|v (half)
__device__ __half g_eln[(size_t)E_MAX * 128];   // ln1e / alpha / ln2e (half)
__device__ __half g_ep [(size_t)E_MAX * 128];   // ep (half)
__device__ float  g_dist[(size_t)E_MAX];
__device__ float  g_wV [(size_t)N_MAX * 128];
__device__ float  g_z  [(size_t)N_MAX * 8];
__device__ __half g_t  [(size_t)E_MAX * 256];   // FFN hidden (half)
__device__ __half g_wT [229376];                // transposed half weights
__device__ int    g_is64;

// ---------------------------------------------------------------------------
// MMA + cp.async primitives
// ---------------------------------------------------------------------------
__device__ __forceinline__ void mma_f16(float* c, const uint32_t* a,
                                        uint32_t b0, uint32_t b1) {
    asm volatile(
        "mma.sync.aligned.m16n8k16.row.col.f32.f16.f16.f32 "
        "{%0,%1,%2,%3}, {%4,%5,%6,%7}, {%8,%9}, {%0,%1,%2,%3};"
        : "+f"(c[0]), "+f"(c[1]), "+f"(c[2]), "+f"(c[3])
        : "r"(a[0]), "r"(a[1]), "r"(a[2]), "r"(a[3]), "r"(b0), "r"(b1));
}
#define CP16(d, s, n) asm volatile("cp.async.cg.shared.global [%0], [%1], 16, %2;" :: "r"(d), "l"(s), "r"(n) : "memory")
#define CPCOMMIT()    asm volatile("cp.async.commit_group;" ::: "memory")
#define CPWAIT(n)     asm volatile("cp.async.wait_group %0;" :: "n"(n) : "memory")

#define SKH 40
#define BUFB (128 * SKH * 2)
#define CHUNKH (128 * SKH)

// ---------------------------------------------------------------------------
// 256-thread fp16 HMMA GEMM (tile 128x128, BK=32, 4x2 warps, double-buffered)
// Epilogues: +bias, +r1m*r1n, SiLU, +resid; optional fused output LayerNorm.
// ---------------------------------------------------------------------------
__global__ void __launch_bounds__(256, 2) mma_gemm(
    const __half* __restrict__ Ah, int lda,
    const __half* __restrict__ BT,
    float* __restrict__ Cf, __half* __restrict__ Ch,
    int M, int K, int ldc,
    const float* __restrict__ bias,
    const float* __restrict__ resid, int ldr,
    const float* __restrict__ r1m, const float* __restrict__ r1n,
    int act,
    const float* __restrict__ lng, const float* __restrict__ lnb,
    __half* __restrict__ lnout)
{
    __shared__ __half sA[2][CHUNKH];
    __shared__ __half sB[2][CHUNKH];
    __shared__ float red[128][2][2];

    const int tid = threadIdx.x;
    const int wid = tid >> 5;
    const int lane = tid & 31;
    const int warp_m = wid & 3;
    const int warp_n = wid >> 2;
    const int m0 = blockIdx.x * 128;
    const int n0 = blockIdx.y * 128;
    const int grp = lane >> 2;
    const int tig = lane & 3;

    const uint32_t sA0 = (uint32_t)__cvta_generic_to_shared(&sA[0][0]);
    const uint32_t sB0 = (uint32_t)__cvta_generic_to_shared(&sB[0][0]);
    const int arow = tid >> 2, aj = tid & 3;

    float acc[2][8][4];
    #pragma unroll
    for (int t = 0; t < 2; t++)
        #pragma unroll
        for (int j = 0; j < 8; j++)
            #pragma unroll
            for (int c = 0; c < 4; c++) acc[t][j][c] = 0.0f;

    const int nc = K >> 5;

    auto loadB = [&](int c, int buf) {
        const int k0 = c << 5;
        #pragma unroll
        for (int i = 0; i < 2; i++) {
            const int row = arow + i * 64;
            const uint32_t dst = sB0 + buf * BUFB + row * (SKH * 2) + aj * 16;
            const __half* src = BT + (size_t)(n0 + row) * K + k0 + aj * 8;
            CP16(dst, src, 16);
        }
    };
    auto loadA = [&](int c, int buf) {
        const int k0 = c << 5;
        #pragma unroll
        for (int i = 0; i < 2; i++) {
            const int row = arow + i * 64;
            const uint32_t dst = sA0 + buf * BUFB + row * (SKH * 2) + aj * 16;
            const int ok = (m0 + row) < M;
            const __half* src = Ah + (size_t)(ok ? (m0 + row) : 0) * lda + k0 + aj * 8;
            CP16(dst, src, ok ? 16 : 0);
        }
    };
    auto compute = [&](int buf) {
        const __half* Ab = &sA[buf][0];
        const __half* Bb = &sB[buf][0];
        #pragma unroll
        for (int ks = 0; ks < 2; ks++) {
            const int kk = ks * 16;
            uint32_t a[2][4];
            #pragma unroll
            for (int t = 0; t < 2; t++) {
                const __half* ap = Ab + (warp_m * 32 + t * 16 + grp) * SKH + kk + 2 * tig;
                a[t][0] = *(const uint32_t*)(ap);
                a[t][1] = *(const uint32_t*)(ap + 8 * SKH);
                a[t][2] = *(const uint32_t*)(ap + 8);
                a[t][3] = *(const uint32_t*)(ap + 8 * SKH + 8);
            }
            #pragma unroll
            for (int j = 0; j < 8; j++) {
                const __half* bp = Bb + (warp_n * 64 + j * 8 + grp) * SKH + kk + 2 * tig;
                const uint32_t b0 = *(const uint32_t*)(bp);
                const uint32_t b1 = *(const uint32_t*)(bp + 8);
                mma_f16(acc[0][j], a[0], b0, b1);
                mma_f16(acc[1][j], a[1], b0, b1);
            }
        }
    };

    loadA(0, 0); loadB(0, 0); CPCOMMIT();
    for (int c = 0; c < nc; c++) {
        if (c + 1 < nc) {
            loadA(c + 1, (c + 1) & 1); loadB(c + 1, (c + 1) & 1);
            CPCOMMIT(); CPWAIT(1);
        } else CPWAIT(0);
        __syncthreads();
        compute(c & 1);
        __syncthreads();
    }

    if (lng == nullptr) {
        #pragma unroll
        for (int t = 0; t < 2; t++) {
            #pragma unroll
            for (int hh = 0; hh < 2; hh++) {
                const int m = m0 + warp_m * 32 + t * 16 + grp + hh * 8;
                if (m >= M) continue;
                const float r1 = r1m ? r1m[m] : 0.0f;
                const float* rrow = resid ? resid + (size_t)m * ldr : nullptr;
                #pragma unroll
                for (int j = 0; j < 8; j++) {
                    const int col = n0 + warp_n * 64 + j * 8 + tig * 2;
                    float v0 = acc[t][j][hh * 2 + 0];
                    float v1 = acc[t][j][hh * 2 + 1];
                    if (bias) { v0 += bias[col]; v1 += bias[col + 1]; }
                    if (r1m)  { v0 += r1 * r1n[col]; v1 += r1 * r1n[col + 1]; }
                    if (act) {
                        v0 = v0 / (1.0f + __expf(-v0));
                        v1 = v1 / (1.0f + __expf(-v1));
                    }
                    if (resid) { v0 += rrow[col]; v1 += rrow[col + 1]; }
                    if (Ch) {
                        *(__half2*)(Ch + (size_t)m * ldc + col) = __floats2half2_rn(v0, v1);
                    } else {
                        float2 o2; o2.x = v0; o2.y = v1;
                        *(float2*)(Cf + (size_t)m * ldc + col) = o2;
                    }
                }
            }
        }
    } else {
        // fused bias+resid -> Cf (fp32), then LayerNorm -> lnout (half)
        float s[2][2], sq[2][2];
        #pragma unroll
        for (int t = 0; t < 2; t++) {
            #pragma unroll
            for (int hh = 0; hh < 2; hh++) {
                const int m = m0 + warp_m * 32 + t * 16 + grp + hh * 8;
                const bool ok = m < M;
                const float* rrow = ok ? resid + (size_t)m * ldr : nullptr;
                float sum = 0.f, sumsq = 0.f;
                #pragma unroll
                for (int j = 0; j < 8; j++) {
                    const int col = warp_n * 64 + j * 8 + tig * 2;
                    float v0 = acc[t][j][hh * 2 + 0] + bias[col];
                    float v1 = acc[t][j][hh * 2 + 1] + bias[col + 1];
                    if (ok) { v0 += rrow[col]; v1 += rrow[col + 1]; }
                    acc[t][j][hh * 2 + 0] = v0;
                    acc[t][j][hh * 2 + 1] = v1;
                    if (ok) {
                        float2 o2; o2.x = v0; o2.y = v1;
                        *(float2*)(Cf + (size_t)m * ldc + col) = o2;
                    }
                    sum += v0 + v1;
                    sumsq += v0 * v0 + v1 * v1;
                }
                s[t][hh] = sum; sq[t][hh] = sumsq;
            }
        }
        #pragma unroll
        for (int t = 0; t < 2; t++)
            #pragma unroll
            for (int hh = 0; hh < 2; hh++) {
                s[t][hh]  += __shfl_xor_sync(0xffffffffu, s[t][hh], 1);
                s[t][hh]  += __shfl_xor_sync(0xffffffffu, s[t][hh], 2);
                sq[t][hh] += __shfl_xor_sync(0xffffffffu, sq[t][hh], 1);
                sq[t][hh] += __shfl_xor_sync(0xffffffffu, sq[t][hh], 2);
            }
        if (tig == 0) {
            #pragma unroll
            for (int t = 0; t < 2; t++)
                #pragma unroll
                for (int hh = 0; hh < 2; hh++) {
                    const int row = warp_m * 32 + t * 16 + hh * 8 + grp;
                    red[row][warp_n][0] = s[t][hh];
                    red[row][warp_n][1] = sq[t][hh];
                }
        }
        __syncthreads();
        #pragma unroll
        for (int t = 0; t < 2; t++) {
            #pragma unroll
            for (int hh = 0; hh < 2; hh++) {
                const int row = warp_m * 32 + t * 16 + hh * 8 + grp;
                const int m = m0 + row;
                if (m >= M) continue;
                const float S = red[row][0][0] + red[row][1][0];
                const float Q = red[row][0][1] + red[row][1][1];
                const float mu = S * (1.0f / 128.0f);
                const float var = Q * (1.0f / 128.0f) - mu * mu;
                const float rs = rsqrtf(var + 1e-5f);
                #pragma unroll
                for (int j = 0; j < 8; j++) {
                    const int col = warp_n * 64 + j * 8 + tig * 2;
                    float v0 = (acc[t][j][hh * 2 + 0] - mu) * rs * lng[col] + lnb[col];
                    float v1 = (acc[t][j][hh * 2 + 1] - mu) * rs * lng[col + 1] + lnb[col + 1];
                    *(__half2*)(lnout + (size_t)m * 128 + col) = __floats2half2_rn(v0, v1);
                }
            }
        }
    }
}

// ---------------------------------------------------------------------------
// Batched weight transpose to half
// ---------------------------------------------------------------------------
struct TransBatch {
    const float* src[10];
    __half* dst[10];
    int R[10], C[10];
};

__global__ void transpose_all(TransBatch tb)
{
    __shared__ float tile[32][33];
    const int i = blockIdx.z;
    const int R = tb.R[i], Cc = tb.C[i];
    const int c0 = blockIdx.x * 32, r0 = blockIdx.y * 32;
    if (c0 >= Cc || r0 >= R) return;
    const float* src = tb.src[i];
    __half* dst = tb.dst[i];
    int tx = threadIdx.x, ty = threadIdx.y;
    for (int dy = 0; dy < 32; dy += 8) {
        int r = r0 + ty + dy, c = c0 + tx;
        if (r < R && c < Cc) tile[ty + dy][tx] = src[(size_t)r * Cc + c];
    }
    __syncthreads();
    for (int dy = 0; dy < 32; dy += 8) {
        int c = c0 + ty + dy, r = r0 + tx;
        if (r < R && c < Cc) dst[(size_t)c * R + r] = __float2half_rn(tile[tx][ty + dy]);
    }
}

// ---------------------------------------------------------------------------
// misc kernels
// ---------------------------------------------------------------------------
__global__ void detect_kernel(const int* __restrict__ ei32)
{
    if (threadIdx.x == 0 && blockIdx.x == 0) {
        int any = 0;
        #pragma unroll 8
        for (int i = 0; i < 64; i++) any |= ei32[2 * i + 1];
        g_is64 = (any == 0) ? 1 : 0;
    }
}
__device__ __forceinline__ int edge_idx(const void* __restrict__ ei, long long pos)
{
    if (g_is64) return (int)((const long long*)ei)[pos];
    return ((const int*)ei)[pos];
}

// merged LayerNorm: rows [0,M1) from set 1, rows [M1,M1+M2) from set 2
__global__ void ln2_kernel(const float* __restrict__ x1,
                           const float* __restrict__ g1, const float* __restrict__ b1,
                           __half* __restrict__ o1, int M1,
                           const float* __restrict__ x2,
                           const float* __restrict__ g2, const float* __restrict__ b2,
                           __half* __restrict__ o2, int M2)
{
    int w = (blockIdx.x * blockDim.x + threadIdx.x) >> 5;
    int lane = threadIdx.x & 31;
    const float *x, *g, *b; __half* o; int row;
    if (w < M1) { x = x1; g = g1; b = b1; o = o1; row = w; }
    else if (w < M1 + M2) { x = x2; g = g2; b = b2; o = o2; row = w - M1; }
    else return;
    float4 v = *(const float4*)(x + (size_t)row * 128 + lane * 4);
    float s  = v.x + v.y + v.z + v.w;
    float sq = v.x*v.x + v.y*v.y + v.z*v.z + v.w*v.w;
    #pragma unroll
    for (int off = 16; off; off >>= 1) {
        s  += __shfl_xor_sync(0xffffffffu, s,  off);
        sq += __shfl_xor_sync(0xffffffffu, sq, off);
    }
    float mu  = s * (1.0f / 128.0f);
    float var = sq * (1.0f / 128.0f) - mu * mu;
    float rs  = rsqrtf(var + 1e-5f);
    float4 gv = *(const float4*)(g + lane * 4);
    float4 bv = *(const float4*)(b + lane * 4);
    __half2 h0 = __floats2half2_rn((v.x - mu) * rs * gv.x + bv.x,
                                   (v.y - mu) * rs * gv.y + bv.y);
    __half2 h1 = __floats2half2_rn((v.z - mu) * rs * gv.z + bv.z,
                                   (v.w - mu) * rs * gv.w + bv.w);
    uint2 u; u.x = *(uint32_t*)&h0; u.y = *(uint32_t*)&h1;
    *(uint2*)(o + (size_t)row * 128 + lane * 4) = u;
}

__global__ void dist_kernel(const float* __restrict__ coords,
                            const void* __restrict__ ei,
                            float* __restrict__ dist, int E)
{
    int e = blockIdx.x * blockDim.x + threadIdx.x;
    if (e >= E) return;
    int r = edge_idx(ei, e);
    int c = edge_idx(ei, (long long)E + e);
    float dx = coords[r * 3 + 0] - coords[c * 3 + 0];
    float dy = coords[r * 3 + 1] - coords[c * 3 + 1];
    float dz = coords[r * 3 + 2] - coords[c * 3 + 2];
    dist[e] = 0.1f * sqrtf(dx * dx + dy * dy + dz * dz);
}

// edge attention: 16 lanes per edge (2 edges/warp), uint4 loads,
// vector red.global for segment sums.
__global__ void attn_edge_kernel(const __half* __restrict__ qkv,
                                 const __half* __restrict__ ep,
                                 __half* __restrict__ alpha_h,
                                 const void* __restrict__ ei,
                                 float* __restrict__ wV,
                                 float* __restrict__ z,
                                 int E)
{
    const int idx = blockIdx.x * blockDim.x + threadIdx.x;
    const int e = idx >> 4;           // edge id
    const int l = threadIdx.x & 15;   // lane within edge (8 halfs each)
    if (e >= E) return;
    const int r = edge_idx(ei, e);
    const int c = edge_idx(ei, (long long)E + e);

    const uint4 qu = *(const uint4*)(qkv + (size_t)c * 384 + l * 8);
    const uint4 ku = *(const uint4*)(qkv + (size_t)r * 384 + 128 + l * 8);
    const uint4 vu = *(const uint4*)(qkv + (size_t)r * 384 + 256 + l * 8);
    const uint4 eu = *(const uint4*)(ep + (size_t)e * 128 + l * 8);

    float a[8], vv[8];
    float hs = 0.0f;
    #pragma unroll
    for (int i = 0; i < 4; i++) {
        const uint32_t qw = (&qu.x)[i], kw = (&ku.x)[i];
        const uint32_t vw = (&vu.x)[i], ew = (&eu.x)[i];
        const float2 qf = __half22float2(*(const __half2*)&qw);
        const float2 kf = __half22float2(*(const __half2*)&kw);
        const float2 vf = __half22float2(*(const __half2*)&vw);
        const float2 ef = __half22float2(*(const __half2*)&ew);
        float a0 = fminf(fmaxf(kf.x * qf.x * 0.25f, -5.0f), 5.0f) * ef.x;
        float a1 = fminf(fmaxf(kf.y * qf.y * 0.25f, -5.0f), 5.0f) * ef.y;
        a[i * 2 + 0] = a0; a[i * 2 + 1] = a1;
        vv[i * 2 + 0] = vf.x; vv[i * 2 + 1] = vf.y;
        hs += a0 + a1;
    }

    uint4 au;
    #pragma unroll
    for (int i = 0; i < 4; i++) {
        __half2 h = __floats2half2_rn(a[i * 2], a[i * 2 + 1]);
        (&au.x)[i] = *(uint32_t*)&h;
    }
    *(uint4*)(alpha_h + (size_t)e * 128 + l * 8) = au;

    // head h = lanes {2h, 2h+1}
    hs += __shfl_xor_sync(0xffffffffu, hs, 1);
    const float ax = __expf(fminf(fmaxf(hs, -5.0f), 5.0f));

    float* wvp = wV + (size_t)c * 128 + l * 8;
    asm volatile("red.global.add.v4.f32 [%0], {%1, %2, %3, %4};"
                 :: "l"(wvp), "f"(vv[0] * ax), "f"(vv[1] * ax),
                    "f"(vv[2] * ax), "f"(vv[3] * ax) : "memory");
    asm volatile("red.global.add.v4.f32 [%0], {%1, %2, %3, %4};"
                 :: "l"(wvp + 4), "f"(vv[4] * ax), "f"(vv[5] * ax),
                    "f"(vv[6] * ax), "f"(vv[7] * ax) : "memory");
    if ((l & 1) == 0)
        asm volatile("red.global.add.f32 [%0], %1;"
                     :: "l"(z + (size_t)c * 8 + (l >> 1)), "f"(ax) : "memory");
}

__global__ void hattn_kernel(const float* __restrict__ wV,
                             const float* __restrict__ z,
                             __half* __restrict__ out, int N)
{
    int i = blockIdx.x * blockDim.x + threadIdx.x;
    if (i >= N * 128) return;
    int n = i >> 7;
    int h = (i & 127) >> 4;
    out[i] = __float2half_rn(wV[i] / (z[(size_t)n * 8 + h] + 1e-6f));
}

// ---------------------------------------------------------------------------
// Launch
// ---------------------------------------------------------------------------
extern "C" void kernel_launch(void* const* d_in, const int* in_sizes, int n_in,
                              void* d_out, int out_size)
{
    const float* node_feats = (const float*)d_in[0];
    const float* edge_feats = (const float*)d_in[1];
    const float* coords     = (const float*)d_in[2];
    const void*  ei         = d_in[3];
    const float* Wq   = (const float*)d_in[4];
    const float* Wk   = (const float*)d_in[5];
    const float* Wv   = (const float*)d_in[6];
    const float* We   = (const float*)d_in[7];
    const float* Wo_n = (const float*)d_in[8];
    const float* bo_n = (const float*)d_in[9];
    const float* Wo_e = (const float*)d_in[10];
    const float* bo_e = (const float*)d_in[11];
    const float* ln1n_g = (const float*)d_in[12];
    const float* ln1n_b = (const float*)d_in[13];
    const float* ln1e_g = (const float*)d_in[14];
    const float* ln1e_b = (const float*)d_in[15];
    const float* ln2n_g = (const float*)d_in[16];
    const float* ln2n_b = (const float*)d_in[17];
    const float* ln2e_g = (const float*)d_in[18];
    const float* ln2e_b = (const float*)d_in[19];
    const float* Wn1 = (const float*)d_in[20];
    const float* Wn2 = (const float*)d_in[21];
    const float* We1 = (const float*)d_in[22];
    const float* We2 = (const float*)d_in[23];

    int N = in_sizes[0] / 128;
    int E = in_sizes[1] / 128;

    float* out   = (float*)d_out;
    float* out_n = out;
    float* out_e = out + (size_t)N * 128;

    __half *p_hln, *p_qkv, *p_eln, *p_ep, *p_t, *p_wT;
    float *p_dist, *p_wV, *p_z;
    cudaGetSymbolAddress((void**)&p_hln,  g_hln);
    cudaGetSymbolAddress((void**)&p_qkv,  g_qkv);
    cudaGetSymbolAddress((void**)&p_eln,  g_eln);
    cudaGetSymbolAddress((void**)&p_ep,   g_ep);
    cudaGetSymbolAddress((void**)&p_dist, g_dist);
    cudaGetSymbolAddress((void**)&p_wV,   g_wV);
    cudaGetSymbolAddress((void**)&p_z,    g_z);
    cudaGetSymbolAddress((void**)&p_t,    g_t);
    cudaGetSymbolAddress((void**)&p_wT,   g_wT);

    __half* WqkvT = p_wT + 0;        // [384,128]
    __half* WeT   = p_wT + 49152;    // [128,128]
    __half* WonT  = p_wT + 65536;
    __half* WoeT  = p_wT + 81920;
    __half* Wn1T  = p_wT + 98304;    // [256,128]
    __half* Wn2T  = p_wT + 131072;   // [128,256]
    __half* We1T  = p_wT + 163840;
    __half* We2T  = p_wT + 196608;

    dim3 blk(256);

    detect_kernel<<<1, 32>>>((const int*)ei);

    {
        TransBatch tb;
        const float* srcs[10] = {Wq, Wk, Wv, We, Wo_n, Wo_e, Wn1, Wn2, We1, We2};
        __half* dsts[10] = {WqkvT, WqkvT + 16384, WqkvT + 32768, WeT, WonT, WoeT,
                            Wn1T, Wn2T, We1T, We2T};
        int Rs[10] = {128, 128, 128, 128, 128, 128, 128, 256, 128, 256};
        int Cs[10] = {128, 128, 128, 128, 128, 128, 256, 128, 256, 128};
        for (int i = 0; i < 10; i++) {
            tb.src[i] = srcs[i]; tb.dst[i] = dsts[i]; tb.R[i] = Rs[i]; tb.C[i] = Cs[i];
        }
        transpose_all<<<dim3(8, 8, 10), dim3(32, 8)>>>(tb);
    }

    // merged LN1 (nodes + edges), dist, async zero-fill
    ln2_kernel<<<(N + E + 7) / 8, blk>>>(node_feats, ln1n_g, ln1n_b, p_hln, N,
                                         edge_feats, ln1e_g, ln1e_b, p_eln, E);
    dist_kernel<<<(E + 255) / 256, blk>>>(coords, ei, p_dist, E);
    cudaMemsetAsync(p_wV, 0, (size_t)N * 128 * sizeof(float), 0);
    cudaMemsetAsync(p_z,  0, (size_t)N * 8 * sizeof(float), 0);

    const int gN = (N + 127) / 128;
    const int gE = (E + 127) / 128;

    // qkv fused: [N,128]h @ [128,384] -> half
    mma_gemm<<<dim3(gN, 3), blk>>>(p_hln, 128, WqkvT, nullptr, p_qkv,
                                   N, 128, 384, nullptr, nullptr, 0,
                                   nullptr, nullptr, 0, nullptr, nullptr, nullptr);

    // ep = LN(e) @ We[0:128] + dist (x) We[128] -> half
    mma_gemm<<<dim3(gE, 1), blk>>>(p_eln, 128, WeT, nullptr, p_ep,
                                   E, 128, 128, nullptr, nullptr, 0,
                                   p_dist, We + 128 * 128, 0, nullptr, nullptr, nullptr);

    // attention: alpha (half) into p_eln; reductions into wV, z
    attn_edge_kernel<<<(E + 15) / 16, blk>>>(p_qkv, p_ep, p_eln, ei, p_wV, p_z, E);
    hattn_kernel<<<(N * 128 + 255) / 256, blk>>>(p_wV, p_z, p_hln, N);

    // h2 = node_feats + h_attn @ Wo_n + bo_n; fused LN2n -> p_hln
    mma_gemm<<<dim3(gN, 1), blk>>>(p_hln, 128, WonT, out_n, nullptr,
                                   N, 128, 128, bo_n, node_feats, 128,
                                   nullptr, nullptr, 0, ln2n_g, ln2n_b, p_hln);
    // e2 = edge_feats + alpha @ Wo_e + bo_e; fused LN2e -> p_eln
    mma_gemm<<<dim3(gE, 1), blk>>>(p_eln, 128, WoeT, out_e, nullptr,
                                   E, 128, 128, bo_e, edge_feats, 128,
                                   nullptr, nullptr, 0, ln2e_g, ln2e_b, p_eln);

    // node FFN
    mma_gemm<<<dim3(gN, 2), blk>>>(p_hln, 128, Wn1T, nullptr, p_t,
                                   N, 128, 256, nullptr, nullptr, 0,
                                   nullptr, nullptr, 1, nullptr, nullptr, nullptr);
    mma_gemm<<<dim3(gN, 1), blk>>>(p_t, 256, Wn2T, out_n, nullptr,
                                   N, 256, 128, nullptr, out_n, 128,
                                   nullptr, nullptr, 0, nullptr, nullptr, nullptr);

    // edge FFN
    mma_gemm<<<dim3(gE, 2), blk>>>(p_eln, 128, We1T, nullptr, p_t,
                                   E, 128, 256, nullptr, nullptr, 0,
                                   nullptr, nullptr, 1, nullptr, nullptr, nullptr);
    mma_gemm<<<dim3(gE, 1), blk>>>(p_t, 256, We2T, out_e, nullptr,
                                   E, 256, 128, nullptr, out_e, 128,
                                   nullptr, nullptr, 0, nullptr, nullptr, nullptr);
}

// round 14
// speedup vs baseline: 1.0813x; 1.0298x over previous
#include <cuda_runtime.h>
#include <cuda_fp16.h>
#include <math.h>
#include <stdint.h>

// ---------------------------------------------------------------------------
// GraphTransformer layer: N=50000, E=600000, C=128, H=8, Dh=16
// Round 14: round-13 champion kernels, unchanged + fork/join stream overlap
// (node path concurrent with edge path) inside graph capture.
// ---------------------------------------------------------------------------

#define N_MAX 50000
#define E_MAX 600000

__device__ __half g_hln[(size_t)N_MAX * 128];   // ln1n / h_attn / ln2n (half)
__device__ __half g_qkv[(size_t)N_MAX * 384];   // q|k|v (half)
__device__ __half g_eln[(size_t)E_MAX * 128];   // ln1e / alpha / ln2e (half)
__device__ __half g_ep [(size_t)E_MAX * 128];   // ep (half)
__device__ float  g_dist[(size_t)E_MAX];
__device__ float  g_wV [(size_t)N_MAX * 128];
__device__ float  g_z  [(size_t)N_MAX * 8];
__device__ __half g_t  [(size_t)E_MAX * 256];   // edge FFN hidden (half)
__device__ __half g_tn [(size_t)N_MAX * 256];   // node FFN hidden (half)
__device__ __half g_wT [229376];                // transposed half weights
__device__ int    g_is64;

// ---------------------------------------------------------------------------
// MMA + cp.async primitives
// ---------------------------------------------------------------------------
__device__ __forceinline__ void mma_f16(float* c, const uint32_t* a,
                                        uint32_t b0, uint32_t b1) {
    asm volatile(
        "mma.sync.aligned.m16n8k16.row.col.f32.f16.f16.f32 "
        "{%0,%1,%2,%3}, {%4,%5,%6,%7}, {%8,%9}, {%0,%1,%2,%3};"
        : "+f"(c[0]), "+f"(c[1]), "+f"(c[2]), "+f"(c[3])
        : "r"(a[0]), "r"(a[1]), "r"(a[2]), "r"(a[3]), "r"(b0), "r"(b1));
}
#define CP16(d, s, n) asm volatile("cp.async.cg.shared.global [%0], [%1], 16, %2;" :: "r"(d), "l"(s), "r"(n) : "memory")
#define CPCOMMIT()    asm volatile("cp.async.commit_group;" ::: "memory")
#define CPWAIT(n)     asm volatile("cp.async.wait_group %0;" :: "n"(n) : "memory")

#define SKH 40
#define BUFB (128 * SKH * 2)
#define CHUNKH (128 * SKH)

// ---------------------------------------------------------------------------
// 256-thread fp16 HMMA GEMM (tile 128x128, BK=32, 4x2 warps, double-buffered)
// Epilogues: +bias, +r1m*r1n, SiLU, +resid; optional fused output LayerNorm.
// ---------------------------------------------------------------------------
__global__ void __launch_bounds__(256, 2) mma_gemm(
    const __half* __restrict__ Ah, int lda,
    const __half* __restrict__ BT,
    float* __restrict__ Cf, __half* __restrict__ Ch,
    int M, int K, int ldc,
    const float* __restrict__ bias,
    const float* __restrict__ resid, int ldr,
    const float* __restrict__ r1m, const float* __restrict__ r1n,
    int act,
    const float* __restrict__ lng, const float* __restrict__ lnb,
    __half* __restrict__ lnout)
{
    __shared__ __half sA[2][CHUNKH];
    __shared__ __half sB[2][CHUNKH];
    __shared__ float red[128][2][2];

    const int tid = threadIdx.x;
    const int wid = tid >> 5;
    const int lane = tid & 31;
    const int warp_m = wid & 3;
    const int warp_n = wid >> 2;
    const int m0 = blockIdx.x * 128;
    const int n0 = blockIdx.y * 128;
    const int grp = lane >> 2;
    const int tig = lane & 3;

    const uint32_t sA0 = (uint32_t)__cvta_generic_to_shared(&sA[0][0]);
    const uint32_t sB0 = (uint32_t)__cvta_generic_to_shared(&sB[0][0]);
    const int arow = tid >> 2, aj = tid & 3;

    float acc[2][8][4];
    #pragma unroll
    for (int t = 0; t < 2; t++)
        #pragma unroll
        for (int j = 0; j < 8; j++)
            #pragma unroll
            for (int c = 0; c < 4; c++) acc[t][j][c] = 0.0f;

    const int nc = K >> 5;

    auto loadB = [&](int c, int buf) {
        const int k0 = c << 5;
        #pragma unroll
        for (int i = 0; i < 2; i++) {
            const int row = arow + i * 64;
            const uint32_t dst = sB0 + buf * BUFB + row * (SKH * 2) + aj * 16;
            const __half* src = BT + (size_t)(n0 + row) * K + k0 + aj * 8;
            CP16(dst, src, 16);
        }
    };
    auto loadA = [&](int c, int buf) {
        const int k0 = c << 5;
        #pragma unroll
        for (int i = 0; i < 2; i++) {
            const int row = arow + i * 64;
            const uint32_t dst = sA0 + buf * BUFB + row * (SKH * 2) + aj * 16;
            const int ok = (m0 + row) < M;
            const __half* src = Ah + (size_t)(ok ? (m0 + row) : 0) * lda + k0 + aj * 8;
            CP16(dst, src, ok ? 16 : 0);
        }
    };
    auto compute = [&](int buf) {
        const __half* Ab = &sA[buf][0];
        const __half* Bb = &sB[buf][0];
        #pragma unroll
        for (int ks = 0; ks < 2; ks++) {
            const int kk = ks * 16;
            uint32_t a[2][4];
            #pragma unroll
            for (int t = 0; t < 2; t++) {
                const __half* ap = Ab + (warp_m * 32 + t * 16 + grp) * SKH + kk + 2 * tig;
                a[t][0] = *(const uint32_t*)(ap);
                a[t][1] = *(const uint32_t*)(ap + 8 * SKH);
                a[t][2] = *(const uint32_t*)(ap + 8);
                a[t][3] = *(const uint32_t*)(ap + 8 * SKH + 8);
            }
            #pragma unroll
            for (int j = 0; j < 8; j++) {
                const __half* bp = Bb + (warp_n * 64 + j * 8 + grp) * SKH + kk + 2 * tig;
                const uint32_t b0 = *(const uint32_t*)(bp);
                const uint32_t b1 = *(const uint32_t*)(bp + 8);
                mma_f16(acc[0][j], a[0], b0, b1);
                mma_f16(acc[1][j], a[1], b0, b1);
            }
        }
    };

    loadA(0, 0); loadB(0, 0); CPCOMMIT();
    for (int c = 0; c < nc; c++) {
        if (c + 1 < nc) {
            loadA(c + 1, (c + 1) & 1); loadB(c + 1, (c + 1) & 1);
            CPCOMMIT(); CPWAIT(1);
        } else CPWAIT(0);
        __syncthreads();
        compute(c & 1);
        __syncthreads();
    }

    if (lng == nullptr) {
        #pragma unroll
        for (int t = 0; t < 2; t++) {
            #pragma unroll
            for (int hh = 0; hh < 2; hh++) {
                const int m = m0 + warp_m * 32 + t * 16 + grp + hh * 8;
                if (m >= M) continue;
                const float r1 = r1m ? r1m[m] : 0.0f;
                const float* rrow = resid ? resid + (size_t)m * ldr : nullptr;
                #pragma unroll
                for (int j = 0; j < 8; j++) {
                    const int col = n0 + warp_n * 64 + j * 8 + tig * 2;
                    float v0 = acc[t][j][hh * 2 + 0];
                    float v1 = acc[t][j][hh * 2 + 1];
                    if (bias) { v0 += bias[col]; v1 += bias[col + 1]; }
                    if (r1m)  { v0 += r1 * r1n[col]; v1 += r1 * r1n[col + 1]; }
                    if (act) {
                        v0 = v0 / (1.0f + __expf(-v0));
                        v1 = v1 / (1.0f + __expf(-v1));
                    }
                    if (resid) { v0 += rrow[col]; v1 += rrow[col + 1]; }
                    if (Ch) {
                        *(__half2*)(Ch + (size_t)m * ldc + col) = __floats2half2_rn(v0, v1);
                    } else {
                        float2 o2; o2.x = v0; o2.y = v1;
                        *(float2*)(Cf + (size_t)m * ldc + col) = o2;
                    }
                }
            }
        }
    } else {
        // fused bias+resid -> Cf (fp32), then LayerNorm -> lnout (half)
        float s[2][2], sq[2][2];
        #pragma unroll
        for (int t = 0; t < 2; t++) {
            #pragma unroll
            for (int hh = 0; hh < 2; hh++) {
                const int m = m0 + warp_m * 32 + t * 16 + grp + hh * 8;
                const bool ok = m < M;
                const float* rrow = ok ? resid + (size_t)m * ldr : nullptr;
                float sum = 0.f, sumsq = 0.f;
                #pragma unroll
                for (int j = 0; j < 8; j++) {
                    const int col = warp_n * 64 + j * 8 + tig * 2;
                    float v0 = acc[t][j][hh * 2 + 0] + bias[col];
                    float v1 = acc[t][j][hh * 2 + 1] + bias[col + 1];
                    if (ok) { v0 += rrow[col]; v1 += rrow[col + 1]; }
                    acc[t][j][hh * 2 + 0] = v0;
                    acc[t][j][hh * 2 + 1] = v1;
                    if (ok) {
                        float2 o2; o2.x = v0; o2.y = v1;
                        *(float2*)(Cf + (size_t)m * ldc + col) = o2;
                    }
                    sum += v0 + v1;
                    sumsq += v0 * v0 + v1 * v1;
                }
                s[t][hh] = sum; sq[t][hh] = sumsq;
            }
        }
        #pragma unroll
        for (int t = 0; t < 2; t++)
            #pragma unroll
            for (int hh = 0; hh < 2; hh++) {
                s[t][hh]  += __shfl_xor_sync(0xffffffffu, s[t][hh], 1);
                s[t][hh]  += __shfl_xor_sync(0xffffffffu, s[t][hh], 2);
                sq[t][hh] += __shfl_xor_sync(0xffffffffu, sq[t][hh], 1);
                sq[t][hh] += __shfl_xor_sync(0xffffffffu, sq[t][hh], 2);
            }
        if (tig == 0) {
            #pragma unroll
            for (int t = 0; t < 2; t++)
                #pragma unroll
                for (int hh = 0; hh < 2; hh++) {
                    const int row = warp_m * 32 + t * 16 + hh * 8 + grp;
                    red[row][warp_n][0] = s[t][hh];
                    red[row][warp_n][1] = sq[t][hh];
                }
        }
        __syncthreads();
        #pragma unroll
        for (int t = 0; t < 2; t++) {
            #pragma unroll
            for (int hh = 0; hh < 2; hh++) {
                const int row = warp_m * 32 + t * 16 + hh * 8 + grp;
                const int m = m0 + row;
                if (m >= M) continue;
                const float S = red[row][0][0] + red[row][1][0];
                const float Q = red[row][0][1] + red[row][1][1];
                const float mu = S * (1.0f / 128.0f);
                const float var = Q * (1.0f / 128.0f) - mu * mu;
                const float rs = rsqrtf(var + 1e-5f);
                #pragma unroll
                for (int j = 0; j < 8; j++) {
                    const int col = warp_n * 64 + j * 8 + tig * 2;
                    float v0 = (acc[t][j][hh * 2 + 0] - mu) * rs * lng[col] + lnb[col];
                    float v1 = (acc[t][j][hh * 2 + 1] - mu) * rs * lng[col + 1] + lnb[col + 1];
                    *(__half2*)(lnout + (size_t)m * 128 + col) = __floats2half2_rn(v0, v1);
                }
            }
        }
    }
}

// ---------------------------------------------------------------------------
// Batched weight transpose to half
// ---------------------------------------------------------------------------
struct TransBatch {
    const float* src[10];
    __half* dst[10];
    int R[10], C[10];
};

__global__ void transpose_all(TransBatch tb)
{
    __shared__ float tile[32][33];
    const int i = blockIdx.z;
    const int R = tb.R[i], Cc = tb.C[i];
    const int c0 = blockIdx.x * 32, r0 = blockIdx.y * 32;
    if (c0 >= Cc || r0 >= R) return;
    const float* src = tb.src[i];
    __half* dst = tb.dst[i];
    int tx = threadIdx.x, ty = threadIdx.y;
    for (int dy = 0; dy < 32; dy += 8) {
        int r = r0 + ty + dy, c = c0 + tx;
        if (r < R && c < Cc) tile[ty + dy][tx] = src[(size_t)r * Cc + c];
    }
    __syncthreads();
    for (int dy = 0; dy < 32; dy += 8) {
        int c = c0 + ty + dy, r = r0 + tx;
        if (r < R && c < Cc) dst[(size_t)c * R + r] = __float2half_rn(tile[tx][ty + dy]);
    }
}

// ---------------------------------------------------------------------------
// misc kernels
// ---------------------------------------------------------------------------
__global__ void detect_kernel(const int* __restrict__ ei32)
{
    if (threadIdx.x == 0 && blockIdx.x == 0) {
        int any = 0;
        #pragma unroll 8
        for (int i = 0; i < 64; i++) any |= ei32[2 * i + 1];
        g_is64 = (any == 0) ? 1 : 0;
    }
}
__device__ __forceinline__ int edge_idx(const void* __restrict__ ei, long long pos)
{
    if (g_is64) return (int)((const long long*)ei)[pos];
    return ((const int*)ei)[pos];
}

// merged LayerNorm: rows [0,M1) from set 1, rows [M1,M1+M2) from set 2
__global__ void ln2_kernel(const float* __restrict__ x1,
                           const float* __restrict__ g1, const float* __restrict__ b1,
                           __half* __restrict__ o1, int M1,
                           const float* __restrict__ x2,
                           const float* __restrict__ g2, const float* __restrict__ b2,
                           __half* __restrict__ o2, int M2)
{
    int w = (blockIdx.x * blockDim.x + threadIdx.x) >> 5;
    int lane = threadIdx.x & 31;
    const float *x, *g, *b; __half* o; int row;
    if (w < M1) { x = x1; g = g1; b = b1; o = o1; row = w; }
    else if (w < M1 + M2) { x = x2; g = g2; b = b2; o = o2; row = w - M1; }
    else return;
    float4 v = *(const float4*)(x + (size_t)row * 128 + lane * 4);
    float s  = v.x + v.y + v.z + v.w;
    float sq = v.x*v.x + v.y*v.y + v.z*v.z + v.w*v.w;
    #pragma unroll
    for (int off = 16; off; off >>= 1) {
        s  += __shfl_xor_sync(0xffffffffu, s,  off);
        sq += __shfl_xor_sync(0xffffffffu, sq, off);
    }
    float mu  = s * (1.0f / 128.0f);
    float var = sq * (1.0f / 128.0f) - mu * mu;
    float rs  = rsqrtf(var + 1e-5f);
    float4 gv = *(const float4*)(g + lane * 4);
    float4 bv = *(const float4*)(b + lane * 4);
    __half2 h0 = __floats2half2_rn((v.x - mu) * rs * gv.x + bv.x,
                                   (v.y - mu) * rs * gv.y + bv.y);
    __half2 h1 = __floats2half2_rn((v.z - mu) * rs * gv.z + bv.z,
                                   (v.w - mu) * rs * gv.w + bv.w);
    uint2 u; u.x = *(uint32_t*)&h0; u.y = *(uint32_t*)&h1;
    *(uint2*)(o + (size_t)row * 128 + lane * 4) = u;
}

__global__ void dist_kernel(const float* __restrict__ coords,
                            const void* __restrict__ ei,
                            float* __restrict__ dist, int E)
{
    int e = blockIdx.x * blockDim.x + threadIdx.x;
    if (e >= E) return;
    int r = edge_idx(ei, e);
    int c = edge_idx(ei, (long long)E + e);
    float dx = coords[r * 3 + 0] - coords[c * 3 + 0];
    float dy = coords[r * 3 + 1] - coords[c * 3 + 1];
    float dz = coords[r * 3 + 2] - coords[c * 3 + 2];
    dist[e] = 0.1f * sqrtf(dx * dx + dy * dy + dz * dz);
}

// edge attention: 16 lanes per edge (2 edges/warp), uint4 loads,
// vector red.global for segment sums.
__global__ void attn_edge_kernel(const __half* __restrict__ qkv,
                                 const __half* __restrict__ ep,
                                 __half* __restrict__ alpha_h,
                                 const void* __restrict__ ei,
                                 float* __restrict__ wV,
                                 float* __restrict__ z,
                                 int E)
{
    const int idx = blockIdx.x * blockDim.x + threadIdx.x;
    const int e = idx >> 4;           // edge id
    const int l = threadIdx.x & 15;   // lane within edge (8 halfs each)
    if (e >= E) return;
    const int r = edge_idx(ei, e);
    const int c = edge_idx(ei, (long long)E + e);

    const uint4 qu = *(const uint4*)(qkv + (size_t)c * 384 + l * 8);
    const uint4 ku = *(const uint4*)(qkv + (size_t)r * 384 + 128 + l * 8);
    const uint4 vu = *(const uint4*)(qkv + (size_t)r * 384 + 256 + l * 8);
    const uint4 eu = *(const uint4*)(ep + (size_t)e * 128 + l * 8);

    float a[8], vv[8];
    float hs = 0.0f;
    #pragma unroll
    for (int i = 0; i < 4; i++) {
        const uint32_t qw = (&qu.x)[i], kw = (&ku.x)[i];
        const uint32_t vw = (&vu.x)[i], ew = (&eu.x)[i];
        const float2 qf = __half22float2(*(const __half2*)&qw);
        const float2 kf = __half22float2(*(const __half2*)&kw);
        const float2 vf = __half22float2(*(const __half2*)&vw);
        const float2 ef = __half22float2(*(const __half2*)&ew);
        float a0 = fminf(fmaxf(kf.x * qf.x * 0.25f, -5.0f), 5.0f) * ef.x;
        float a1 = fminf(fmaxf(kf.y * qf.y * 0.25f, -5.0f), 5.0f) * ef.y;
        a[i * 2 + 0] = a0; a[i * 2 + 1] = a1;
        vv[i * 2 + 0] = vf.x; vv[i * 2 + 1] = vf.y;
        hs += a0 + a1;
    }

    uint4 au;
    #pragma unroll
    for (int i = 0; i < 4; i++) {
        __half2 h = __floats2half2_rn(a[i * 2], a[i * 2 + 1]);
        (&au.x)[i] = *(uint32_t*)&h;
    }
    *(uint4*)(alpha_h + (size_t)e * 128 + l * 8) = au;

    // head h = lanes {2h, 2h+1}
    hs += __shfl_xor_sync(0xffffffffu, hs, 1);
    const float ax = __expf(fminf(fmaxf(hs, -5.0f), 5.0f));

    float* wvp = wV + (size_t)c * 128 + l * 8;
    asm volatile("red.global.add.v4.f32 [%0], {%1, %2, %3, %4};"
                 :: "l"(wvp), "f"(vv[0] * ax), "f"(vv[1] * ax),
                    "f"(vv[2] * ax), "f"(vv[3] * ax) : "memory");
    asm volatile("red.global.add.v4.f32 [%0], {%1, %2, %3, %4};"
                 :: "l"(wvp + 4), "f"(vv[4] * ax), "f"(vv[5] * ax),
                    "f"(vv[6] * ax), "f"(vv[7] * ax) : "memory");
    if ((l & 1) == 0)
        asm volatile("red.global.add.f32 [%0], %1;"
                     :: "l"(z + (size_t)c * 8 + (l >> 1)), "f"(ax) : "memory");
}

__global__ void hattn_kernel(const float* __restrict__ wV,
                             const float* __restrict__ z,
                             __half* __restrict__ out, int N)
{
    int i = blockIdx.x * blockDim.x + threadIdx.x;
    if (i >= N * 128) return;
    int n = i >> 7;
    int h = (i & 127) >> 4;
    out[i] = __float2half_rn(wV[i] / (z[(size_t)n * 8 + h] + 1e-6f));
}

// ---------------------------------------------------------------------------
// Launch (fork/join two-stream schedule, graph-capture compatible)
// ---------------------------------------------------------------------------
extern "C" void kernel_launch(void* const* d_in, const int* in_sizes, int n_in,
                              void* d_out, int out_size)
{
    const float* node_feats = (const float*)d_in[0];
    const float* edge_feats = (const float*)d_in[1];
    const float* coords     = (const float*)d_in[2];
    const void*  ei         = d_in[3];
    const float* Wq   = (const float*)d_in[4];
    const float* Wk   = (const float*)d_in[5];
    const float* Wv   = (const float*)d_in[6];
    const float* We   = (const float*)d_in[7];
    const float* Wo_n = (const float*)d_in[8];
    const float* bo_n = (const float*)d_in[9];
    const float* Wo_e = (const float*)d_in[10];
    const float* bo_e = (const float*)d_in[11];
    const float* ln1n_g = (const float*)d_in[12];
    const float* ln1n_b = (const float*)d_in[13];
    const float* ln1e_g = (const float*)d_in[14];
    const float* ln1e_b = (const float*)d_in[15];
    const float* ln2n_g = (const float*)d_in[16];
    const float* ln2n_b = (const float*)d_in[17];
    const float* ln2e_g = (const float*)d_in[18];
    const float* ln2e_b = (const float*)d_in[19];
    const float* Wn1 = (const float*)d_in[20];
    const float* Wn2 = (const float*)d_in[21];
    const float* We1 = (const float*)d_in[22];
    const float* We2 = (const float*)d_in[23];

    int N = in_sizes[0] / 128;
    int E = in_sizes[1] / 128;

    float* out   = (float*)d_out;
    float* out_n = out;
    float* out_e = out + (size_t)N * 128;

    __half *p_hln, *p_qkv, *p_eln, *p_ep, *p_t, *p_tn, *p_wT;
    float *p_dist, *p_wV, *p_z;
    cudaGetSymbolAddress((void**)&p_hln,  g_hln);
    cudaGetSymbolAddress((void**)&p_qkv,  g_qkv);
    cudaGetSymbolAddress((void**)&p_eln,  g_eln);
    cudaGetSymbolAddress((void**)&p_ep,   g_ep);
    cudaGetSymbolAddress((void**)&p_dist, g_dist);
    cudaGetSymbolAddress((void**)&p_wV,   g_wV);
    cudaGetSymbolAddress((void**)&p_z,    g_z);
    cudaGetSymbolAddress((void**)&p_t,    g_t);
    cudaGetSymbolAddress((void**)&p_tn,   g_tn);
    cudaGetSymbolAddress((void**)&p_wT,   g_wT);

    __half* WqkvT = p_wT + 0;        // [384,128]
    __half* WeT   = p_wT + 49152;    // [128,128]
    __half* WonT  = p_wT + 65536;
    __half* WoeT  = p_wT + 81920;
    __half* Wn1T  = p_wT + 98304;    // [256,128]
    __half* Wn2T  = p_wT + 131072;   // [128,256]
    __half* We1T  = p_wT + 163840;
    __half* We2T  = p_wT + 196608;

    dim3 blk(256);
    cudaStream_t s0 = 0;

    // second stream + fork/join events (fresh each call; never destroyed
    // mid-capture — kernel_launch is invoked only a handful of times)
    cudaStream_t s2;
    cudaEvent_t evA, evB, evC;
    cudaStreamCreateWithFlags(&s2, cudaStreamNonBlocking);
    cudaEventCreateWithFlags(&evA, cudaEventDisableTiming);
    cudaEventCreateWithFlags(&evB, cudaEventDisableTiming);
    cudaEventCreateWithFlags(&evC, cudaEventDisableTiming);

    detect_kernel<<<1, 32, 0, s0>>>((const int*)ei);

    {
        TransBatch tb;
        const float* srcs[10] = {Wq, Wk, Wv, We, Wo_n, Wo_e, Wn1, Wn2, We1, We2};
        __half* dsts[10] = {WqkvT, WqkvT + 16384, WqkvT + 32768, WeT, WonT, WoeT,
                            Wn1T, Wn2T, We1T, We2T};
        int Rs[10] = {128, 128, 128, 128, 128, 128, 128, 256, 128, 256};
        int Cs[10] = {128, 128, 128, 128, 128, 128, 256, 128, 256, 128};
        for (int i = 0; i < 10; i++) {
            tb.src[i] = srcs[i]; tb.dst[i] = dsts[i]; tb.R[i] = Rs[i]; tb.C[i] = Cs[i];
        }
        transpose_all<<<dim3(8, 8, 10), dim3(32, 8), 0, s0>>>(tb);
    }

    // LN1 (nodes + edges merged)
    ln2_kernel<<<(N + E + 7) / 8, blk, 0, s0>>>(node_feats, ln1n_g, ln1n_b, p_hln, N,
                                                edge_feats, ln1e_g, ln1e_b, p_eln, E);

    const int gN = (N + 127) / 128;
    const int gE = (E + 127) / 128;

    // ---- fork A: node qkv on s2 concurrent with edge dist/ep on s0 ----
    cudaEventRecord(evA, s0);
    cudaStreamWaitEvent(s2, evA, 0);

    // s2 (node): qkv fused [N,128]h @ [128,384] -> half
    mma_gemm<<<dim3(gN, 3), blk, 0, s2>>>(p_hln, 128, WqkvT, nullptr, p_qkv,
                                          N, 128, 384, nullptr, nullptr, 0,
                                          nullptr, nullptr, 0, nullptr, nullptr, nullptr);

    // s0 (edge): dist, memsets, ep GEMM
    dist_kernel<<<(E + 255) / 256, blk, 0, s0>>>(coords, ei, p_dist, E);
    cudaMemsetAsync(p_wV, 0, (size_t)N * 128 * sizeof(float), s0);
    cudaMemsetAsync(p_z,  0, (size_t)N * 8 * sizeof(float), s0);
    mma_gemm<<<dim3(gE, 1), blk, 0, s0>>>(p_eln, 128, WeT, nullptr, p_ep,
                                          E, 128, 128, nullptr, nullptr, 0,
                                          p_dist, We + 128 * 128, 0, nullptr, nullptr, nullptr);

    // join A: attention (s0) needs qkv (s2)
    cudaEventRecord(evB, s2);
    cudaStreamWaitEvent(s0, evB, 0);

    // attention: alpha (half) into p_eln; reductions into wV, z
    attn_edge_kernel<<<(E + 15) / 16, blk, 0, s0>>>(p_qkv, p_ep, p_eln, ei, p_wV, p_z, E);

    // ---- fork B: node path on s2 concurrent with edge path on s0 ----
    cudaEventRecord(evA, s0);
    cudaStreamWaitEvent(s2, evA, 0);

    // s2 (node): hattn -> Wo_n(+LN2n) -> node FFN -> out_n
    hattn_kernel<<<(N * 128 + 255) / 256, blk, 0, s2>>>(p_wV, p_z, p_hln, N);
    mma_gemm<<<dim3(gN, 1), blk, 0, s2>>>(p_hln, 128, WonT, out_n, nullptr,
                                          N, 128, 128, bo_n, node_feats, 128,
                                          nullptr, nullptr, 0, ln2n_g, ln2n_b, p_hln);
    mma_gemm<<<dim3(gN, 2), blk, 0, s2>>>(p_hln, 128, Wn1T, nullptr, p_tn,
                                          N, 128, 256, nullptr, nullptr, 0,
                                          nullptr, nullptr, 1, nullptr, nullptr, nullptr);
    mma_gemm<<<dim3(gN, 1), blk, 0, s2>>>(p_tn, 256, Wn2T, out_n, nullptr,
                                          N, 256, 128, nullptr, out_n, 128,
                                          nullptr, nullptr, 0, nullptr, nullptr, nullptr);

    // s0 (edge): Wo_e(+LN2e) -> edge FFN -> out_e
    mma_gemm<<<dim3(gE, 1), blk, 0, s0>>>(p_eln, 128, WoeT, out_e, nullptr,
                                          E, 128, 128, bo_e, edge_feats, 128,
                                          nullptr, nullptr, 0, ln2e_g, ln2e_b, p_eln);
    mma_gemm<<<dim3(gE, 2), blk, 0, s0>>>(p_eln, 128, We1T, nullptr, p_t,
                                          E, 128, 256, nullptr, nullptr, 0,
                                          nullptr, nullptr, 1, nullptr, nullptr, nullptr);
    mma_gemm<<<dim3(gE, 1), blk, 0, s0>>>(p_t, 256, We2T, out_e, nullptr,
                                          E, 256, 128, nullptr, out_e, 128,
                                          nullptr, nullptr, 0, nullptr, nullptr, nullptr);

    // join B: everything back on s0 before return
    cudaEventRecord(evC, s2);
    cudaStreamWaitEvent(s0, evC, 0);
}

// round 15
// speedup vs baseline: 1.1060x; 1.0228x over previous
#include <cuda_runtime.h>
#include <cuda_fp16.h>
#include <math.h>
#include <stdint.h>

// ---------------------------------------------------------------------------
// GraphTransformer layer: N=50000, E=600000, C=128, H=8, Dh=16
// Round 15: round-14 (stream overlap) + ldmatrix.x4 fragment loads in the
// GEMM mainloop (6 LDSM vs 24 LDS.32 per k-step).
// ---------------------------------------------------------------------------

#define N_MAX 50000
#define E_MAX 600000

__device__ __half g_hln[(size_t)N_MAX * 128];   // ln1n / h_attn / ln2n (half)
__device__ __half g_qkv[(size_t)N_MAX * 384];   // q|k|v (half)
__device__ __half g_eln[(size_t)E_MAX * 128];   // ln1e / alpha / ln2e (half)
__device__ __half g_ep [(size_t)E_MAX * 128];   // ep (half)
__device__ float  g_dist[(size_t)E_MAX];
__device__ float  g_wV [(size_t)N_MAX * 128];
__device__ float  g_z  [(size_t)N_MAX * 8];
__device__ __half g_t  [(size_t)E_MAX * 256];   // edge FFN hidden (half)
__device__ __half g_tn [(size_t)N_MAX * 256];   // node FFN hidden (half)
__device__ __half g_wT [229376];                // transposed half weights
__device__ int    g_is64;

// ---------------------------------------------------------------------------
// MMA + cp.async + ldmatrix primitives
// ---------------------------------------------------------------------------
__device__ __forceinline__ void mma_f16(float* c, const uint32_t* a,
                                        uint32_t b0, uint32_t b1) {
    asm volatile(
        "mma.sync.aligned.m16n8k16.row.col.f32.f16.f16.f32 "
        "{%0,%1,%2,%3}, {%4,%5,%6,%7}, {%8,%9}, {%0,%1,%2,%3};"
        : "+f"(c[0]), "+f"(c[1]), "+f"(c[2]), "+f"(c[3])
        : "r"(a[0]), "r"(a[1]), "r"(a[2]), "r"(a[3]), "r"(b0), "r"(b1));
}
__device__ __forceinline__ void ldsm_x4(uint32_t* r, uint32_t addr) {
    asm volatile("ldmatrix.sync.aligned.m8n8.x4.shared.b16 {%0,%1,%2,%3}, [%4];"
                 : "=r"(r[0]), "=r"(r[1]), "=r"(r[2]), "=r"(r[3]) : "r"(addr));
}
#define CP16(d, s, n) asm volatile("cp.async.cg.shared.global [%0], [%1], 16, %2;" :: "r"(d), "l"(s), "r"(n) : "memory")
#define CPCOMMIT()    asm volatile("cp.async.commit_group;" ::: "memory")
#define CPWAIT(n)     asm volatile("cp.async.wait_group %0;" :: "n"(n) : "memory")

#define SKH 40
#define BUFB (128 * SKH * 2)
#define CHUNKH (128 * SKH)

// ---------------------------------------------------------------------------
// 256-thread fp16 HMMA GEMM (tile 128x128, BK=32, 4x2 warps, double-buffered,
// ldmatrix fragment loads).
// Epilogues: +bias, +r1m*r1n, SiLU, +resid; optional fused output LayerNorm.
// ---------------------------------------------------------------------------
__global__ void __launch_bounds__(256, 2) mma_gemm(
    const __half* __restrict__ Ah, int lda,
    const __half* __restrict__ BT,
    float* __restrict__ Cf, __half* __restrict__ Ch,
    int M, int K, int ldc,
    const float* __restrict__ bias,
    const float* __restrict__ resid, int ldr,
    const float* __restrict__ r1m, const float* __restrict__ r1n,
    int act,
    const float* __restrict__ lng, const float* __restrict__ lnb,
    __half* __restrict__ lnout)
{
    __shared__ __half sA[2][CHUNKH];
    __shared__ __half sB[2][CHUNKH];
    __shared__ float red[128][2][2];

    const int tid = threadIdx.x;
    const int wid = tid >> 5;
    const int lane = tid & 31;
    const int warp_m = wid & 3;
    const int warp_n = wid >> 2;
    const int m0 = blockIdx.x * 128;
    const int n0 = blockIdx.y * 128;
    const int grp = lane >> 2;
    const int tig = lane & 3;

    const uint32_t sA0 = (uint32_t)__cvta_generic_to_shared(&sA[0][0]);
    const uint32_t sB0 = (uint32_t)__cvta_generic_to_shared(&sB[0][0]);
    const int arow = tid >> 2, aj = tid & 3;

    // ldmatrix per-lane address components
    const int lr8  = lane & 7;
    const int aSel = (lane >> 3) & 1;      // +8 rows for frag 1/3
    const int aK   = (lane >> 4) * 8;      // +8 halfs for frag 2/3
    const int bJ   = lane >> 4;            // j within pair (0/1)
    const int bK   = ((lane >> 3) & 1) * 8;
    // base row offsets (halfs) within the tile
    const uint32_t aOffH = (uint32_t)((warp_m * 32 + aSel * 8 + lr8) * SKH + aK);
    const uint32_t bOffH = (uint32_t)((warp_n * 64 + bJ * 8 + lr8) * SKH + bK);

    float acc[2][8][4];
    #pragma unroll
    for (int t = 0; t < 2; t++)
        #pragma unroll
        for (int j = 0; j < 8; j++)
            #pragma unroll
            for (int c = 0; c < 4; c++) acc[t][j][c] = 0.0f;

    const int nc = K >> 5;

    auto loadB = [&](int c, int buf) {
        const int k0 = c << 5;
        #pragma unroll
        for (int i = 0; i < 2; i++) {
            const int row = arow + i * 64;
            const uint32_t dst = sB0 + buf * BUFB + row * (SKH * 2) + aj * 16;
            const __half* src = BT + (size_t)(n0 + row) * K + k0 + aj * 8;
            CP16(dst, src, 16);
        }
    };
    auto loadA = [&](int c, int buf) {
        const int k0 = c << 5;
        #pragma unroll
        for (int i = 0; i < 2; i++) {
            const int row = arow + i * 64;
            const uint32_t dst = sA0 + buf * BUFB + row * (SKH * 2) + aj * 16;
            const int ok = (m0 + row) < M;
            const __half* src = Ah + (size_t)(ok ? (m0 + row) : 0) * lda + k0 + aj * 8;
            CP16(dst, src, ok ? 16 : 0);
        }
    };
    auto compute = [&](int buf) {
        const uint32_t abase = sA0 + buf * BUFB + aOffH * 2;
        const uint32_t bbase = sB0 + buf * BUFB + bOffH * 2;
        #pragma unroll
        for (int ks = 0; ks < 2; ks++) {
            const uint32_t koff = (uint32_t)(ks * 16 * 2);
            uint32_t a0[4], a1[4];
            ldsm_x4(a0, abase + koff);
            ldsm_x4(a1, abase + koff + 16 * SKH * 2);
            #pragma unroll
            for (int jp = 0; jp < 4; jp++) {
                uint32_t b[4];
                ldsm_x4(b, bbase + koff + (uint32_t)(jp * 16 * SKH * 2));
                mma_f16(acc[0][jp * 2 + 0], a0, b[0], b[1]);
                mma_f16(acc[1][jp * 2 + 0], a1, b[0], b[1]);
                mma_f16(acc[0][jp * 2 + 1], a0, b[2], b[3]);
                mma_f16(acc[1][jp * 2 + 1], a1, b[2], b[3]);
            }
        }
    };

    loadA(0, 0); loadB(0, 0); CPCOMMIT();
    for (int c = 0; c < nc; c++) {
        if (c + 1 < nc) {
            loadA(c + 1, (c + 1) & 1); loadB(c + 1, (c + 1) & 1);
            CPCOMMIT(); CPWAIT(1);
        } else CPWAIT(0);
        __syncthreads();
        compute(c & 1);
        __syncthreads();
    }

    if (lng == nullptr) {
        #pragma unroll
        for (int t = 0; t < 2; t++) {
            #pragma unroll
            for (int hh = 0; hh < 2; hh++) {
                const int m = m0 + warp_m * 32 + t * 16 + grp + hh * 8;
                if (m >= M) continue;
                const float r1 = r1m ? r1m[m] : 0.0f;
                const float* rrow = resid ? resid + (size_t)m * ldr : nullptr;
                #pragma unroll
                for (int j = 0; j < 8; j++) {
                    const int col = n0 + warp_n * 64 + j * 8 + tig * 2;
                    float v0 = acc[t][j][hh * 2 + 0];
                    float v1 = acc[t][j][hh * 2 + 1];
                    if (bias) { v0 += bias[col]; v1 += bias[col + 1]; }
                    if (r1m)  { v0 += r1 * r1n[col]; v1 += r1 * r1n[col + 1]; }
                    if (act) {
                        v0 = v0 / (1.0f + __expf(-v0));
                        v1 = v1 / (1.0f + __expf(-v1));
                    }
                    if (resid) { v0 += rrow[col]; v1 += rrow[col + 1]; }
                    if (Ch) {
                        *(__half2*)(Ch + (size_t)m * ldc + col) = __floats2half2_rn(v0, v1);
                    } else {
                        float2 o2; o2.x = v0; o2.y = v1;
                        *(float2*)(Cf + (size_t)m * ldc + col) = o2;
                    }
                }
            }
        }
    } else {
        // fused bias+resid -> Cf (fp32), then LayerNorm -> lnout (half)
        float s[2][2], sq[2][2];
        #pragma unroll
        for (int t = 0; t < 2; t++) {
            #pragma unroll
            for (int hh = 0; hh < 2; hh++) {
                const int m = m0 + warp_m * 32 + t * 16 + grp + hh * 8;
                const bool ok = m < M;
                const float* rrow = ok ? resid + (size_t)m * ldr : nullptr;
                float sum = 0.f, sumsq = 0.f;
                #pragma unroll
                for (int j = 0; j < 8; j++) {
                    const int col = warp_n * 64 + j * 8 + tig * 2;
                    float v0 = acc[t][j][hh * 2 + 0] + bias[col];
                    float v1 = acc[t][j][hh * 2 + 1] + bias[col + 1];
                    if (ok) { v0 += rrow[col]; v1 += rrow[col + 1]; }
                    acc[t][j][hh * 2 + 0] = v0;
                    acc[t][j][hh * 2 + 1] = v1;
                    if (ok) {
                        float2 o2; o2.x = v0; o2.y = v1;
                        *(float2*)(Cf + (size_t)m * ldc + col) = o2;
                    }
                    sum += v0 + v1;
                    sumsq += v0 * v0 + v1 * v1;
                }
                s[t][hh] = sum; sq[t][hh] = sumsq;
            }
        }
        #pragma unroll
        for (int t = 0; t < 2; t++)
            #pragma unroll
            for (int hh = 0; hh < 2; hh++) {
                s[t][hh]  += __shfl_xor_sync(0xffffffffu, s[t][hh], 1);
                s[t][hh]  += __shfl_xor_sync(0xffffffffu, s[t][hh], 2);
                sq[t][hh] += __shfl_xor_sync(0xffffffffu, sq[t][hh], 1);
                sq[t][hh] += __shfl_xor_sync(0xffffffffu, sq[t][hh], 2);
            }
        if (tig == 0) {
            #pragma unroll
            for (int t = 0; t < 2; t++)
                #pragma unroll
                for (int hh = 0; hh < 2; hh++) {
                    const int row = warp_m * 32 + t * 16 + hh * 8 + grp;
                    red[row][warp_n][0] = s[t][hh];
                    red[row][warp_n][1] = sq[t][hh];
                }
        }
        __syncthreads();
        #pragma unroll
        for (int t = 0; t < 2; t++) {
            #pragma unroll
            for (int hh = 0; hh < 2; hh++) {
                const int row = warp_m * 32 + t * 16 + hh * 8 + grp;
                const int m = m0 + row;
                if (m >= M) continue;
                const float S = red[row][0][0] + red[row][1][0];
                const float Q = red[row][0][1] + red[row][1][1];
                const float mu = S * (1.0f / 128.0f);
                const float var = Q * (1.0f / 128.0f) - mu * mu;
                const float rs = rsqrtf(var + 1e-5f);
                #pragma unroll
                for (int j = 0; j < 8; j++) {
                    const int col = warp_n * 64 + j * 8 + tig * 2;
                    float v0 = (acc[t][j][hh * 2 + 0] - mu) * rs * lng[col] + lnb[col];
                    float v1 = (acc[t][j][hh * 2 + 1] - mu) * rs * lng[col + 1] + lnb[col + 1];
                    *(__half2*)(lnout + (size_t)m * 128 + col) = __floats2half2_rn(v0, v1);
                }
            }
        }
    }
}

// ---------------------------------------------------------------------------
// Batched weight transpose to half
// ---------------------------------------------------------------------------
struct TransBatch {
    const float* src[10];
    __half* dst[10];
    int R[10], C[10];
};

__global__ void transpose_all(TransBatch tb)
{
    __shared__ float tile[32][33];
    const int i = blockIdx.z;
    const int R = tb.R[i], Cc = tb.C[i];
    const int c0 = blockIdx.x * 32, r0 = blockIdx.y * 32;
    if (c0 >= Cc || r0 >= R) return;
    const float* src = tb.src[i];
    __half* dst = tb.dst[i];
    int tx = threadIdx.x, ty = threadIdx.y;
    for (int dy = 0; dy < 32; dy += 8) {
        int r = r0 + ty + dy, c = c0 + tx;
        if (r < R && c < Cc) tile[ty + dy][tx] = src[(size_t)r * Cc + c];
    }
    __syncthreads();
    for (int dy = 0; dy < 32; dy += 8) {
        int c = c0 + ty + dy, r = r0 + tx;
        if (r < R && c < Cc) dst[(size_t)c * R + r] = __float2half_rn(tile[tx][ty + dy]);
    }
}

// ---------------------------------------------------------------------------
// misc kernels
// ---------------------------------------------------------------------------
__global__ void detect_kernel(const int* __restrict__ ei32)
{
    if (threadIdx.x == 0 && blockIdx.x == 0) {
        int any = 0;
        #pragma unroll 8
        for (int i = 0; i < 64; i++) any |= ei32[2 * i + 1];
        g_is64 = (any == 0) ? 1 : 0;
    }
}
__device__ __forceinline__ int edge_idx(const void* __restrict__ ei, long long pos)
{
    if (g_is64) return (int)((const long long*)ei)[pos];
    return ((const int*)ei)[pos];
}

// merged LayerNorm: rows [0,M1) from set 1, rows [M1,M1+M2) from set 2
__global__ void ln2_kernel(const float* __restrict__ x1,
                           const float* __restrict__ g1, const float* __restrict__ b1,
                           __half* __restrict__ o1, int M1,
                           const float* __restrict__ x2,
                           const float* __restrict__ g2, const float* __restrict__ b2,
                           __half* __restrict__ o2, int M2)
{
    int w = (blockIdx.x * blockDim.x + threadIdx.x) >> 5;
    int lane = threadIdx.x & 31;
    const float *x, *g, *b; __half* o; int row;
    if (w < M1) { x = x1; g = g1; b = b1; o = o1; row = w; }
    else if (w < M1 + M2) { x = x2; g = g2; b = b2; o = o2; row = w - M1; }
    else return;
    float4 v = *(const float4*)(x + (size_t)row * 128 + lane * 4);
    float s  = v.x + v.y + v.z + v.w;
    float sq = v.x*v.x + v.y*v.y + v.z*v.z + v.w*v.w;
    #pragma unroll
    for (int off = 16; off; off >>= 1) {
        s  += __shfl_xor_sync(0xffffffffu, s,  off);
        sq += __shfl_xor_sync(0xffffffffu, sq, off);
    }
    float mu  = s * (1.0f / 128.0f);
    float var = sq * (1.0f / 128.0f) - mu * mu;
    float rs  = rsqrtf(var + 1e-5f);
    float4 gv = *(const float4*)(g + lane * 4);
    float4 bv = *(const float4*)(b + lane * 4);
    __half2 h0 = __floats2half2_rn((v.x - mu) * rs * gv.x + bv.x,
                                   (v.y - mu) * rs * gv.y + bv.y);
    __half2 h1 = __floats2half2_rn((v.z - mu) * rs * gv.z + bv.z,
                                   (v.w - mu) * rs * gv.w + bv.w);
    uint2 u; u.x = *(uint32_t*)&h0; u.y = *(uint32_t*)&h1;
    *(uint2*)(o + (size_t)row * 128 + lane * 4) = u;
}

__global__ void dist_kernel(const float* __restrict__ coords,
                            const void* __restrict__ ei,
                            float* __restrict__ dist, int E)
{
    int e = blockIdx.x * blockDim.x + threadIdx.x;
    if (e >= E) return;
    int r = edge_idx(ei, e);
    int c = edge_idx(ei, (long long)E + e);
    float dx = coords[r * 3 + 0] - coords[c * 3 + 0];
    float dy = coords[r * 3 + 1] - coords[c * 3 + 1];
    float dz = coords[r * 3 + 2] - coords[c * 3 + 2];
    dist[e] = 0.1f * sqrtf(dx * dx + dy * dy + dz * dz);
}

// edge attention: 16 lanes per edge (2 edges/warp), uint4 loads,
// vector red.global for segment sums.
__global__ void attn_edge_kernel(const __half* __restrict__ qkv,
                                 const __half* __restrict__ ep,
                                 __half* __restrict__ alpha_h,
                                 const void* __restrict__ ei,
                                 float* __restrict__ wV,
                                 float* __restrict__ z,
                                 int E)
{
    const int idx = blockIdx.x * blockDim.x + threadIdx.x;
    const int e = idx >> 4;           // edge id
    const int l = threadIdx.x & 15;   // lane within edge (8 halfs each)
    if (e >= E) return;
    const int r = edge_idx(ei, e);
    const int c = edge_idx(ei, (long long)E + e);

    const uint4 qu = *(const uint4*)(qkv + (size_t)c * 384 + l * 8);
    const uint4 ku = *(const uint4*)(qkv + (size_t)r * 384 + 128 + l * 8);
    const uint4 vu = *(const uint4*)(qkv + (size_t)r * 384 + 256 + l * 8);
    const uint4 eu = *(const uint4*)(ep + (size_t)e * 128 + l * 8);

    float a[8], vv[8];
    float hs = 0.0f;
    #pragma unroll
    for (int i = 0; i < 4; i++) {
        const uint32_t qw = (&qu.x)[i], kw = (&ku.x)[i];
        const uint32_t vw = (&vu.x)[i], ew = (&eu.x)[i];
        const float2 qf = __half22float2(*(const __half2*)&qw);
        const float2 kf = __half22float2(*(const __half2*)&kw);
        const float2 vf = __half22float2(*(const __half2*)&vw);
        const float2 ef = __half22float2(*(const __half2*)&ew);
        float a0 = fminf(fmaxf(kf.x * qf.x * 0.25f, -5.0f), 5.0f) * ef.x;
        float a1 = fminf(fmaxf(kf.y * qf.y * 0.25f, -5.0f), 5.0f) * ef.y;
        a[i * 2 + 0] = a0; a[i * 2 + 1] = a1;
        vv[i * 2 + 0] = vf.x; vv[i * 2 + 1] = vf.y;
        hs += a0 + a1;
    }

    uint4 au;
    #pragma unroll
    for (int i = 0; i < 4; i++) {
        __half2 h = __floats2half2_rn(a[i * 2], a[i * 2 + 1]);
        (&au.x)[i] = *(uint32_t*)&h;
    }
    *(uint4*)(alpha_h + (size_t)e * 128 + l * 8) = au;

    // head h = lanes {2h, 2h+1}
    hs += __shfl_xor_sync(0xffffffffu, hs, 1);
    const float ax = __expf(fminf(fmaxf(hs, -5.0f), 5.0f));

    float* wvp = wV + (size_t)c * 128 + l * 8;
    asm volatile("red.global.add.v4.f32 [%0], {%1, %2, %3, %4};"
                 :: "l"(wvp), "f"(vv[0] * ax), "f"(vv[1] * ax),
                    "f"(vv[2] * ax), "f"(vv[3] * ax) : "memory");
    asm volatile("red.global.add.v4.f32 [%0], {%1, %2, %3, %4};"
                 :: "l"(wvp + 4), "f"(vv[4] * ax), "f"(vv[5] * ax),
                    "f"(vv[6] * ax), "f"(vv[7] * ax) : "memory");
    if ((l & 1) == 0)
        asm volatile("red.global.add.f32 [%0], %1;"
                     :: "l"(z + (size_t)c * 8 + (l >> 1)), "f"(ax) : "memory");
}

__global__ void hattn_kernel(const float* __restrict__ wV,
                             const float* __restrict__ z,
                             __half* __restrict__ out, int N)
{
    int i = blockIdx.x * blockDim.x + threadIdx.x;
    if (i >= N * 128) return;
    int n = i >> 7;
    int h = (i & 127) >> 4;
    out[i] = __float2half_rn(wV[i] / (z[(size_t)n * 8 + h] + 1e-6f));
}

// ---------------------------------------------------------------------------
// Launch (fork/join two-stream schedule, graph-capture compatible)
// ---------------------------------------------------------------------------
extern "C" void kernel_launch(void* const* d_in, const int* in_sizes, int n_in,
                              void* d_out, int out_size)
{
    const float* node_feats = (const float*)d_in[0];
    const float* edge_feats = (const float*)d_in[1];
    const float* coords     = (const float*)d_in[2];
    const void*  ei         = d_in[3];
    const float* Wq   = (const float*)d_in[4];
    const float* Wk   = (const float*)d_in[5];
    const float* Wv   = (const float*)d_in[6];
    const float* We   = (const float*)d_in[7];
    const float* Wo_n = (const float*)d_in[8];
    const float* bo_n = (const float*)d_in[9];
    const float* Wo_e = (const float*)d_in[10];
    const float* bo_e = (const float*)d_in[11];
    const float* ln1n_g = (const float*)d_in[12];
    const float* ln1n_b = (const float*)d_in[13];
    const float* ln1e_g = (const float*)d_in[14];
    const float* ln1e_b = (const float*)d_in[15];
    const float* ln2n_g = (const float*)d_in[16];
    const float* ln2n_b = (const float*)d_in[17];
    const float* ln2e_g = (const float*)d_in[18];
    const float* ln2e_b = (const float*)d_in[19];
    const float* Wn1 = (const float*)d_in[20];
    const float* Wn2 = (const float*)d_in[21];
    const float* We1 = (const float*)d_in[22];
    const float* We2 = (const float*)d_in[23];

    int N = in_sizes[0] / 128;
    int E = in_sizes[1] / 128;

    float* out   = (float*)d_out;
    float* out_n = out;
    float* out_e = out + (size_t)N * 128;

    __half *p_hln, *p_qkv, *p_eln, *p_ep, *p_t, *p_tn, *p_wT;
    float *p_dist, *p_wV, *p_z;
    cudaGetSymbolAddress((void**)&p_hln,  g_hln);
    cudaGetSymbolAddress((void**)&p_qkv,  g_qkv);
    cudaGetSymbolAddress((void**)&p_eln,  g_eln);
    cudaGetSymbolAddress((void**)&p_ep,   g_ep);
    cudaGetSymbolAddress((void**)&p_dist, g_dist);
    cudaGetSymbolAddress((void**)&p_wV,   g_wV);
    cudaGetSymbolAddress((void**)&p_z,    g_z);
    cudaGetSymbolAddress((void**)&p_t,    g_t);
    cudaGetSymbolAddress((void**)&p_tn,   g_tn);
    cudaGetSymbolAddress((void**)&p_wT,   g_wT);

    __half* WqkvT = p_wT + 0;        // [384,128]
    __half* WeT   = p_wT + 49152;    // [128,128]
    __half* WonT  = p_wT + 65536;
    __half* WoeT  = p_wT + 81920;
    __half* Wn1T  = p_wT + 98304;    // [256,128]
    __half* Wn2T  = p_wT + 131072;   // [128,256]
    __half* We1T  = p_wT + 163840;
    __half* We2T  = p_wT + 196608;

    dim3 blk(256);
    cudaStream_t s0 = 0;

    cudaStream_t s2;
    cudaEvent_t evA, evB, evC;
    cudaStreamCreateWithFlags(&s2, cudaStreamNonBlocking);
    cudaEventCreateWithFlags(&evA, cudaEventDisableTiming);
    cudaEventCreateWithFlags(&evB, cudaEventDisableTiming);
    cudaEventCreateWithFlags(&evC, cudaEventDisableTiming);

    detect_kernel<<<1, 32, 0, s0>>>((const int*)ei);

    {
        TransBatch tb;
        const float* srcs[10] = {Wq, Wk, Wv, We, Wo_n, Wo_e, Wn1, Wn2, We1, We2};
        __half* dsts[10] = {WqkvT, WqkvT + 16384, WqkvT + 32768, WeT, WonT, WoeT,
                            Wn1T, Wn2T, We1T, We2T};
        int Rs[10] = {128, 128, 128, 128, 128, 128, 128, 256, 128, 256};
        int Cs[10] = {128, 128, 128, 128, 128, 128, 256, 128, 256, 128};
        for (int i = 0; i < 10; i++) {
            tb.src[i] = srcs[i]; tb.dst[i] = dsts[i]; tb.R[i] = Rs[i]; tb.C[i] = Cs[i];
        }
        transpose_all<<<dim3(8, 8, 10), dim3(32, 8), 0, s0>>>(tb);
    }

    ln2_kernel<<<(N + E + 7) / 8, blk, 0, s0>>>(node_feats, ln1n_g, ln1n_b, p_hln, N,
                                                edge_feats, ln1e_g, ln1e_b, p_eln, E);

    const int gN = (N + 127) / 128;
    const int gE = (E + 127) / 128;

    // ---- fork A: node qkv on s2 concurrent with edge dist/ep on s0 ----
    cudaEventRecord(evA, s0);
    cudaStreamWaitEvent(s2, evA, 0);

    mma_gemm<<<dim3(gN, 3), blk, 0, s2>>>(p_hln, 128, WqkvT, nullptr, p_qkv,
                                          N, 128, 384, nullptr, nullptr, 0,
                                          nullptr, nullptr, 0, nullptr, nullptr, nullptr);

    dist_kernel<<<(E + 255) / 256, blk, 0, s0>>>(coords, ei, p_dist, E);
    cudaMemsetAsync(p_wV, 0, (size_t)N * 128 * sizeof(float), s0);
    cudaMemsetAsync(p_z,  0, (size_t)N * 8 * sizeof(float), s0);
    mma_gemm<<<dim3(gE, 1), blk, 0, s0>>>(p_eln, 128, WeT, nullptr, p_ep,
                                          E, 128, 128, nullptr, nullptr, 0,
                                          p_dist, We + 128 * 128, 0, nullptr, nullptr, nullptr);

    cudaEventRecord(evB, s2);
    cudaStreamWaitEvent(s0, evB, 0);

    attn_edge_kernel<<<(E + 15) / 16, blk, 0, s0>>>(p_qkv, p_ep, p_eln, ei, p_wV, p_z, E);

    // ---- fork B: node path on s2 concurrent with edge path on s0 ----
    cudaEventRecord(evA, s0);
    cudaStreamWaitEvent(s2, evA, 0);

    hattn_kernel<<<(N * 128 + 255) / 256, blk, 0, s2>>>(p_wV, p_z, p_hln, N);
    mma_gemm<<<dim3(gN, 1), blk, 0, s2>>>(p_hln, 128, WonT, out_n, nullptr,
                                          N, 128, 128, bo_n, node_feats, 128,
                                          nullptr, nullptr, 0, ln2n_g, ln2n_b, p_hln);
    mma_gemm<<<dim3(gN, 2), blk, 0, s2>>>(p_hln, 128, Wn1T, nullptr, p_tn,
                                          N, 128, 256, nullptr, nullptr, 0,
                                          nullptr, nullptr, 1, nullptr, nullptr, nullptr);
    mma_gemm<<<dim3(gN, 1), blk, 0, s2>>>(p_tn, 256, Wn2T, out_n, nullptr,
                                          N, 256, 128, nullptr, out_n, 128,
                                          nullptr, nullptr, 0, nullptr, nullptr, nullptr);

    mma_gemm<<<dim3(gE, 1), blk, 0, s0>>>(p_eln, 128, WoeT, out_e, nullptr,
                                          E, 128, 128, bo_e, edge_feats, 128,
                                          nullptr, nullptr, 0, ln2e_g, ln2e_b, p_eln);
    mma_gemm<<<dim3(gE, 2), blk, 0, s0>>>(p_eln, 128, We1T, nullptr, p_t,
                                          E, 128, 256, nullptr, nullptr, 0,
                                          nullptr, nullptr, 1, nullptr, nullptr, nullptr);
    mma_gemm<<<dim3(gE, 1), blk, 0, s0>>>(p_t, 256, We2T, out_e, nullptr,
                                          E, 256, 128, nullptr, out_e, 128,
                                          nullptr, nullptr, 0, nullptr, nullptr, nullptr);

    cudaEventRecord(evC, s2);
    cudaStreamWaitEvent(s0, evC, 0);
}

// round 16
// speedup vs baseline: 1.1656x; 1.0539x over previous
#include <cuda_runtime.h>
#include <cuda_fp16.h>
#include <math.h>
#include <stdint.h>

// ---------------------------------------------------------------------------
// GraphTransformer layer: N=50000, E=600000, C=128, H=8, Dh=16
// Round 16: round-15 + BK=64 GEMM chunks (dynamic smem, 2 chunks for K=128,
// half the syncs/scoreboard waits). ldmatrix loads, stream overlap kept.
// ---------------------------------------------------------------------------

#define N_MAX 50000
#define E_MAX 600000

__device__ __half g_hln[(size_t)N_MAX * 128];   // ln1n / h_attn / ln2n (half)
__device__ __half g_qkv[(size_t)N_MAX * 384];   // q|k|v (half)
__device__ __half g_eln[(size_t)E_MAX * 128];   // ln1e / alpha / ln2e (half)
__device__ __half g_ep [(size_t)E_MAX * 128];   // ep (half)
__device__ float  g_dist[(size_t)E_MAX];
__device__ float  g_wV [(size_t)N_MAX * 128];
__device__ float  g_z  [(size_t)N_MAX * 8];
__device__ __half g_t  [(size_t)E_MAX * 256];   // edge FFN hidden (half)
__device__ __half g_tn [(size_t)N_MAX * 256];   // node FFN hidden (half)
__device__ __half g_wT [229376];                // transposed half weights
__device__ int    g_is64;

// ---------------------------------------------------------------------------
// MMA + cp.async + ldmatrix primitives
// ---------------------------------------------------------------------------
__device__ __forceinline__ void mma_f16(float* c, const uint32_t* a,
                                        uint32_t b0, uint32_t b1) {
    asm volatile(
        "mma.sync.aligned.m16n8k16.row.col.f32.f16.f16.f32 "
        "{%0,%1,%2,%3}, {%4,%5,%6,%7}, {%8,%9}, {%0,%1,%2,%3};"
        : "+f"(c[0]), "+f"(c[1]), "+f"(c[2]), "+f"(c[3])
        : "r"(a[0]), "r"(a[1]), "r"(a[2]), "r"(a[3]), "r"(b0), "r"(b1));
}
__device__ __forceinline__ void ldsm_x4(uint32_t* r, uint32_t addr) {
    asm volatile("ldmatrix.sync.aligned.m8n8.x4.shared.b16 {%0,%1,%2,%3}, [%4];"
                 : "=r"(r[0]), "=r"(r[1]), "=r"(r[2]), "=r"(r[3]) : "r"(addr));
}
#define CP16(d, s, n) asm volatile("cp.async.cg.shared.global [%0], [%1], 16, %2;" :: "r"(d), "l"(s), "r"(n) : "memory")
#define CPCOMMIT()    asm volatile("cp.async.commit_group;" ::: "memory")
#define CPWAIT(n)     asm volatile("cp.async.wait_group %0;" :: "n"(n) : "memory")

#define BK   64
#define SKH  72                         // halfs per smem row (64 data + 8 pad)
#define TBUFH (128 * SKH)               // halfs per 128xBK tile
#define TBUFB (TBUFH * 2)               // bytes per tile
#define GEMM_DYN (4 * TBUFB)            // A[2] + B[2] = 73728 bytes

// ---------------------------------------------------------------------------
// 256-thread fp16 HMMA GEMM (tile 128x128, BK=64, 4x2 warps, double-buffered,
// ldmatrix fragment loads, dynamic smem).
// Epilogues: +bias, +r1m*r1n, SiLU, +resid; optional fused output LayerNorm.
// ---------------------------------------------------------------------------
__global__ void __launch_bounds__(256, 2) mma_gemm(
    const __half* __restrict__ Ah, int lda,
    const __half* __restrict__ BT,
    float* __restrict__ Cf, __half* __restrict__ Ch,
    int M, int K, int ldc,
    const float* __restrict__ bias,
    const float* __restrict__ resid, int ldr,
    const float* __restrict__ r1m, const float* __restrict__ r1n,
    int act,
    const float* __restrict__ lng, const float* __restrict__ lnb,
    __half* __restrict__ lnout)
{
    extern __shared__ __half dyn[];
    __half* sA = dyn;                   // 2 buffers
    __half* sB = dyn + 2 * TBUFH;       // 2 buffers
    __shared__ float red[128][2][2];

    const int tid = threadIdx.x;
    const int wid = tid >> 5;
    const int lane = tid & 31;
    const int warp_m = wid & 3;
    const int warp_n = wid >> 2;
    const int m0 = blockIdx.x * 128;
    const int n0 = blockIdx.y * 128;
    const int grp = lane >> 2;
    const int tig = lane & 3;

    const uint32_t sA0 = (uint32_t)__cvta_generic_to_shared(sA);
    const uint32_t sB0 = (uint32_t)__cvta_generic_to_shared(sB);
    const int lrow = tid >> 3;          // 0..31
    const int lj   = tid & 7;           // 0..7 (16B granules)

    // ldmatrix per-lane address components
    const int lr8  = lane & 7;
    const int aSel = (lane >> 3) & 1;
    const int aK   = (lane >> 4) * 8;
    const int bJ   = lane >> 4;
    const int bK   = ((lane >> 3) & 1) * 8;
    const uint32_t aOffH = (uint32_t)((warp_m * 32 + aSel * 8 + lr8) * SKH + aK);
    const uint32_t bOffH = (uint32_t)((warp_n * 64 + bJ * 8 + lr8) * SKH + bK);

    float acc[2][8][4];
    #pragma unroll
    for (int t = 0; t < 2; t++)
        #pragma unroll
        for (int j = 0; j < 8; j++)
            #pragma unroll
            for (int c = 0; c < 4; c++) acc[t][j][c] = 0.0f;

    const int nc = K >> 6;   // BK=64 chunks

    auto loadB = [&](int c, int buf) {
        const int k0 = c << 6;
        #pragma unroll
        for (int i = 0; i < 4; i++) {
            const int row = lrow + i * 32;
            const uint32_t dst = sB0 + buf * TBUFB + row * (SKH * 2) + lj * 16;
            const __half* src = BT + (size_t)(n0 + row) * K + k0 + lj * 8;
            CP16(dst, src, 16);
        }
    };
    auto loadA = [&](int c, int buf) {
        const int k0 = c << 6;
        #pragma unroll
        for (int i = 0; i < 4; i++) {
            const int row = lrow + i * 32;
            const uint32_t dst = sA0 + buf * TBUFB + row * (SKH * 2) + lj * 16;
            const int ok = (m0 + row) < M;
            const __half* src = Ah + (size_t)(ok ? (m0 + row) : 0) * lda + k0 + lj * 8;
            CP16(dst, src, ok ? 16 : 0);
        }
    };
    auto compute = [&](int buf) {
        const uint32_t abase = sA0 + buf * TBUFB + aOffH * 2;
        const uint32_t bbase = sB0 + buf * TBUFB + bOffH * 2;
        #pragma unroll
        for (int ks = 0; ks < 4; ks++) {
            const uint32_t koff = (uint32_t)(ks * 16 * 2);
            uint32_t a0[4], a1[4];
            ldsm_x4(a0, abase + koff);
            ldsm_x4(a1, abase + koff + 16 * SKH * 2);
            #pragma unroll
            for (int jp = 0; jp < 4; jp++) {
                uint32_t b[4];
                ldsm_x4(b, bbase + koff + (uint32_t)(jp * 16 * SKH * 2));
                mma_f16(acc[0][jp * 2 + 0], a0, b[0], b[1]);
                mma_f16(acc[1][jp * 2 + 0], a1, b[0], b[1]);
                mma_f16(acc[0][jp * 2 + 1], a0, b[2], b[3]);
                mma_f16(acc[1][jp * 2 + 1], a1, b[2], b[3]);
            }
        }
    };

    loadA(0, 0); loadB(0, 0); CPCOMMIT();
    for (int c = 0; c < nc; c++) {
        if (c + 1 < nc) {
            loadA(c + 1, (c + 1) & 1); loadB(c + 1, (c + 1) & 1);
            CPCOMMIT(); CPWAIT(1);
        } else CPWAIT(0);
        __syncthreads();
        compute(c & 1);
        __syncthreads();
    }

    if (lng == nullptr) {
        #pragma unroll
        for (int t = 0; t < 2; t++) {
            #pragma unroll
            for (int hh = 0; hh < 2; hh++) {
                const int m = m0 + warp_m * 32 + t * 16 + grp + hh * 8;
                if (m >= M) continue;
                const float r1 = r1m ? r1m[m] : 0.0f;
                const float* rrow = resid ? resid + (size_t)m * ldr : nullptr;
                #pragma unroll
                for (int j = 0; j < 8; j++) {
                    const int col = n0 + warp_n * 64 + j * 8 + tig * 2;
                    float v0 = acc[t][j][hh * 2 + 0];
                    float v1 = acc[t][j][hh * 2 + 1];
                    if (bias) { v0 += bias[col]; v1 += bias[col + 1]; }
                    if (r1m)  { v0 += r1 * r1n[col]; v1 += r1 * r1n[col + 1]; }
                    if (act) {
                        v0 = v0 / (1.0f + __expf(-v0));
                        v1 = v1 / (1.0f + __expf(-v1));
                    }
                    if (resid) { v0 += rrow[col]; v1 += rrow[col + 1]; }
                    if (Ch) {
                        *(__half2*)(Ch + (size_t)m * ldc + col) = __floats2half2_rn(v0, v1);
                    } else {
                        float2 o2; o2.x = v0; o2.y = v1;
                        *(float2*)(Cf + (size_t)m * ldc + col) = o2;
                    }
                }
            }
        }
    } else {
        // fused bias+resid -> Cf (fp32), then LayerNorm -> lnout (half)
        float s[2][2], sq[2][2];
        #pragma unroll
        for (int t = 0; t < 2; t++) {
            #pragma unroll
            for (int hh = 0; hh < 2; hh++) {
                const int m = m0 + warp_m * 32 + t * 16 + grp + hh * 8;
                const bool ok = m < M;
                const float* rrow = ok ? resid + (size_t)m * ldr : nullptr;
                float sum = 0.f, sumsq = 0.f;
                #pragma unroll
                for (int j = 0; j < 8; j++) {
                    const int col = warp_n * 64 + j * 8 + tig * 2;
                    float v0 = acc[t][j][hh * 2 + 0] + bias[col];
                    float v1 = acc[t][j][hh * 2 + 1] + bias[col + 1];
                    if (ok) { v0 += rrow[col]; v1 += rrow[col + 1]; }
                    acc[t][j][hh * 2 + 0] = v0;
                    acc[t][j][hh * 2 + 1] = v1;
                    if (ok) {
                        float2 o2; o2.x = v0; o2.y = v1;
                        *(float2*)(Cf + (size_t)m * ldc + col) = o2;
                    }
                    sum += v0 + v1;
                    sumsq += v0 * v0 + v1 * v1;
                }
                s[t][hh] = sum; sq[t][hh] = sumsq;
            }
        }
        #pragma unroll
        for (int t = 0; t < 2; t++)
            #pragma unroll
            for (int hh = 0; hh < 2; hh++) {
                s[t][hh]  += __shfl_xor_sync(0xffffffffu, s[t][hh], 1);
                s[t][hh]  += __shfl_xor_sync(0xffffffffu, s[t][hh], 2);
                sq[t][hh] += __shfl_xor_sync(0xffffffffu, sq[t][hh], 1);
                sq[t][hh] += __shfl_xor_sync(0xffffffffu, sq[t][hh], 2);
            }
        if (tig == 0) {
            #pragma unroll
            for (int t = 0; t < 2; t++)
                #pragma unroll
                for (int hh = 0; hh < 2; hh++) {
                    const int row = warp_m * 32 + t * 16 + hh * 8 + grp;
                    red[row][warp_n][0] = s[t][hh];
                    red[row][warp_n][1] = sq[t][hh];
                }
        }
        __syncthreads();
        #pragma unroll
        for (int t = 0; t < 2; t++) {
            #pragma unroll
            for (int hh = 0; hh < 2; hh++) {
                const int row = warp_m * 32 + t * 16 + hh * 8 + grp;
                const int m = m0 + row;
                if (m >= M) continue;
                const float S = red[row][0][0] + red[row][1][0];
                const float Q = red[row][0][1] + red[row][1][1];
                const float mu = S * (1.0f / 128.0f);
                const float var = Q * (1.0f / 128.0f) - mu * mu;
                const float rs = rsqrtf(var + 1e-5f);
                #pragma unroll
                for (int j = 0; j < 8; j++) {
                    const int col = warp_n * 64 + j * 8 + tig * 2;
                    float v0 = (acc[t][j][hh * 2 + 0] - mu) * rs * lng[col] + lnb[col];
                    float v1 = (acc[t][j][hh * 2 + 1] - mu) * rs * lng[col + 1] + lnb[col + 1];
                    *(__half2*)(lnout + (size_t)m * 128 + col) = __floats2half2_rn(v0, v1);
                }
            }
        }
    }
}

// ---------------------------------------------------------------------------
// Batched weight transpose to half
// ---------------------------------------------------------------------------
struct TransBatch {
    const float* src[10];
    __half* dst[10];
    int R[10], C[10];
};

__global__ void transpose_all(TransBatch tb)
{
    __shared__ float tile[32][33];
    const int i = blockIdx.z;
    const int R = tb.R[i], Cc = tb.C[i];
    const int c0 = blockIdx.x * 32, r0 = blockIdx.y * 32;
    if (c0 >= Cc || r0 >= R) return;
    const float* src = tb.src[i];
    __half* dst = tb.dst[i];
    int tx = threadIdx.x, ty = threadIdx.y;
    for (int dy = 0; dy < 32; dy += 8) {
        int r = r0 + ty + dy, c = c0 + tx;
        if (r < R && c < Cc) tile[ty + dy][tx] = src[(size_t)r * Cc + c];
    }
    __syncthreads();
    for (int dy = 0; dy < 32; dy += 8) {
        int c = c0 + ty + dy, r = r0 + tx;
        if (r < R && c < Cc) dst[(size_t)c * R + r] = __float2half_rn(tile[tx][ty + dy]);
    }
}

// ---------------------------------------------------------------------------
// misc kernels
// ---------------------------------------------------------------------------
__global__ void detect_kernel(const int* __restrict__ ei32)
{
    if (threadIdx.x == 0 && blockIdx.x == 0) {
        int any = 0;
        #pragma unroll 8
        for (int i = 0; i < 64; i++) any |= ei32[2 * i + 1];
        g_is64 = (any == 0) ? 1 : 0;
    }
}
__device__ __forceinline__ int edge_idx(const void* __restrict__ ei, long long pos)
{
    if (g_is64) return (int)((const long long*)ei)[pos];
    return ((const int*)ei)[pos];
}

// merged LayerNorm: rows [0,M1) from set 1, rows [M1,M1+M2) from set 2
__global__ void ln2_kernel(const float* __restrict__ x1,
                           const float* __restrict__ g1, const float* __restrict__ b1,
                           __half* __restrict__ o1, int M1,
                           const float* __restrict__ x2,
                           const float* __restrict__ g2, const float* __restrict__ b2,
                           __half* __restrict__ o2, int M2)
{
    int w = (blockIdx.x * blockDim.x + threadIdx.x) >> 5;
    int lane = threadIdx.x & 31;
    const float *x, *g, *b; __half* o; int row;
    if (w < M1) { x = x1; g = g1; b = b1; o = o1; row = w; }
    else if (w < M1 + M2) { x = x2; g = g2; b = b2; o = o2; row = w - M1; }
    else return;
    float4 v = *(const float4*)(x + (size_t)row * 128 + lane * 4);
    float s  = v.x + v.y + v.z + v.w;
    float sq = v.x*v.x + v.y*v.y + v.z*v.z + v.w*v.w;
    #pragma unroll
    for (int off = 16; off; off >>= 1) {
        s  += __shfl_xor_sync(0xffffffffu, s,  off);
        sq += __shfl_xor_sync(0xffffffffu, sq, off);
    }
    float mu  = s * (1.0f / 128.0f);
    float var = sq * (1.0f / 128.0f) - mu * mu;
    float rs  = rsqrtf(var + 1e-5f);
    float4 gv = *(const float4*)(g + lane * 4);
    float4 bv = *(const float4*)(b + lane * 4);
    __half2 h0 = __floats2half2_rn((v.x - mu) * rs * gv.x + bv.x,
                                   (v.y - mu) * rs * gv.y + bv.y);
    __half2 h1 = __floats2half2_rn((v.z - mu) * rs * gv.z + bv.z,
                                   (v.w - mu) * rs * gv.w + bv.w);
    uint2 u; u.x = *(uint32_t*)&h0; u.y = *(uint32_t*)&h1;
    *(uint2*)(o + (size_t)row * 128 + lane * 4) = u;
}

__global__ void dist_kernel(const float* __restrict__ coords,
                            const void* __restrict__ ei,
                            float* __restrict__ dist, int E)
{
    int e = blockIdx.x * blockDim.x + threadIdx.x;
    if (e >= E) return;
    int r = edge_idx(ei, e);
    int c = edge_idx(ei, (long long)E + e);
    float dx = coords[r * 3 + 0] - coords[c * 3 + 0];
    float dy = coords[r * 3 + 1] - coords[c * 3 + 1];
    float dz = coords[r * 3 + 2] - coords[c * 3 + 2];
    dist[e] = 0.1f * sqrtf(dx * dx + dy * dy + dz * dz);
}

// edge attention: 16 lanes per edge (2 edges/warp), uint4 loads,
// vector red.global for segment sums.
__global__ void attn_edge_kernel(const __half* __restrict__ qkv,
                                 const __half* __restrict__ ep,
                                 __half* __restrict__ alpha_h,
                                 const void* __restrict__ ei,
                                 float* __restrict__ wV,
                                 float* __restrict__ z,
                                 int E)
{
    const int idx = blockIdx.x * blockDim.x + threadIdx.x;
    const int e = idx >> 4;           // edge id
    const int l = threadIdx.x & 15;   // lane within edge (8 halfs each)
    if (e >= E) return;
    const int r = edge_idx(ei, e);
    const int c = edge_idx(ei, (long long)E + e);

    const uint4 qu = *(const uint4*)(qkv + (size_t)c * 384 + l * 8);
    const uint4 ku = *(const uint4*)(qkv + (size_t)r * 384 + 128 + l * 8);
    const uint4 vu = *(const uint4*)(qkv + (size_t)r * 384 + 256 + l * 8);
    const uint4 eu = *(const uint4*)(ep + (size_t)e * 128 + l * 8);

    float a[8], vv[8];
    float hs = 0.0f;
    #pragma unroll
    for (int i = 0; i < 4; i++) {
        const uint32_t qw = (&qu.x)[i], kw = (&ku.x)[i];
        const uint32_t vw = (&vu.x)[i], ew = (&eu.x)[i];
        const float2 qf = __half22float2(*(const __half2*)&qw);
        const float2 kf = __half22float2(*(const __half2*)&kw);
        const float2 vf = __half22float2(*(const __half2*)&vw);
        const float2 ef = __half22float2(*(const __half2*)&ew);
        float a0 = fminf(fmaxf(kf.x * qf.x * 0.25f, -5.0f), 5.0f) * ef.x;
        float a1 = fminf(fmaxf(kf.y * qf.y * 0.25f, -5.0f), 5.0f) * ef.y;
        a[i * 2 + 0] = a0; a[i * 2 + 1] = a1;
        vv[i * 2 + 0] = vf.x; vv[i * 2 + 1] = vf.y;
        hs += a0 + a1;
    }

    uint4 au;
    #pragma unroll
    for (int i = 0; i < 4; i++) {
        __half2 h = __floats2half2_rn(a[i * 2], a[i * 2 + 1]);
        (&au.x)[i] = *(uint32_t*)&h;
    }
    *(uint4*)(alpha_h + (size_t)e * 128 + l * 8) = au;

    // head h = lanes {2h, 2h+1}
    hs += __shfl_xor_sync(0xffffffffu, hs, 1);
    const float ax = __expf(fminf(fmaxf(hs, -5.0f), 5.0f));

    float* wvp = wV + (size_t)c * 128 + l * 8;
    asm volatile("red.global.add.v4.f32 [%0], {%1, %2, %3, %4};"
                 :: "l"(wvp), "f"(vv[0] * ax), "f"(vv[1] * ax),
                    "f"(vv[2] * ax), "f"(vv[3] * ax) : "memory");
    asm volatile("red.global.add.v4.f32 [%0], {%1, %2, %3, %4};"
                 :: "l"(wvp + 4), "f"(vv[4] * ax), "f"(vv[5] * ax),
                    "f"(vv[6] * ax), "f"(vv[7] * ax) : "memory");
    if ((l & 1) == 0)
        asm volatile("red.global.add.f32 [%0], %1;"
                     :: "l"(z + (size_t)c * 8 + (l >> 1)), "f"(ax) : "memory");
}

__global__ void hattn_kernel(const float* __restrict__ wV,
                             const float* __restrict__ z,
                             __half* __restrict__ out, int N)
{
    int i = blockIdx.x * blockDim.x + threadIdx.x;
    if (i >= N * 128) return;
    int n = i >> 7;
    int h = (i & 127) >> 4;
    out[i] = __float2half_rn(wV[i] / (z[(size_t)n * 8 + h] + 1e-6f));
}

// ---------------------------------------------------------------------------
// Launch (fork/join two-stream schedule, graph-capture compatible)
// ---------------------------------------------------------------------------
extern "C" void kernel_launch(void* const* d_in, const int* in_sizes, int n_in,
                              void* d_out, int out_size)
{
    const float* node_feats = (const float*)d_in[0];
    const float* edge_feats = (const float*)d_in[1];
    const float* coords     = (const float*)d_in[2];
    const void*  ei         = d_in[3];
    const float* Wq   = (const float*)d_in[4];
    const float* Wk   = (const float*)d_in[5];
    const float* Wv   = (const float*)d_in[6];
    const float* We   = (const float*)d_in[7];
    const float* Wo_n = (const float*)d_in[8];
    const float* bo_n = (const float*)d_in[9];
    const float* Wo_e = (const float*)d_in[10];
    const float* bo_e = (const float*)d_in[11];
    const float* ln1n_g = (const float*)d_in[12];
    const float* ln1n_b = (const float*)d_in[13];
    const float* ln1e_g = (const float*)d_in[14];
    const float* ln1e_b = (const float*)d_in[15];
    const float* ln2n_g = (const float*)d_in[16];
    const float* ln2n_b = (const float*)d_in[17];
    const float* ln2e_g = (const float*)d_in[18];
    const float* ln2e_b = (const float*)d_in[19];
    const float* Wn1 = (const float*)d_in[20];
    const float* Wn2 = (const float*)d_in[21];
    const float* We1 = (const float*)d_in[22];
    const float* We2 = (const float*)d_in[23];

    int N = in_sizes[0] / 128;
    int E = in_sizes[1] / 128;

    float* out   = (float*)d_out;
    float* out_n = out;
    float* out_e = out + (size_t)N * 128;

    __half *p_hln, *p_qkv, *p_eln, *p_ep, *p_t, *p_tn, *p_wT;
    float *p_dist, *p_wV, *p_z;
    cudaGetSymbolAddress((void**)&p_hln,  g_hln);
    cudaGetSymbolAddress((void**)&p_qkv,  g_qkv);
    cudaGetSymbolAddress((void**)&p_eln,  g_eln);
    cudaGetSymbolAddress((void**)&p_ep,   g_ep);
    cudaGetSymbolAddress((void**)&p_dist, g_dist);
    cudaGetSymbolAddress((void**)&p_wV,   g_wV);
    cudaGetSymbolAddress((void**)&p_z,    g_z);
    cudaGetSymbolAddress((void**)&p_t,    g_t);
    cudaGetSymbolAddress((void**)&p_tn,   g_tn);
    cudaGetSymbolAddress((void**)&p_wT,   g_wT);

    __half* WqkvT = p_wT + 0;        // [384,128]
    __half* WeT   = p_wT + 49152;    // [128,128]
    __half* WonT  = p_wT + 65536;
    __half* WoeT  = p_wT + 81920;
    __half* Wn1T  = p_wT + 98304;    // [256,128]
    __half* Wn2T  = p_wT + 131072;   // [128,256]
    __half* We1T  = p_wT + 163840;
    __half* We2T  = p_wT + 196608;

    dim3 blk(256);
    cudaStream_t s0 = 0;

    cudaFuncSetAttribute(mma_gemm, cudaFuncAttributeMaxDynamicSharedMemorySize,
                         GEMM_DYN);

    cudaStream_t s2;
    cudaEvent_t evA, evB, evC;
    cudaStreamCreateWithFlags(&s2, cudaStreamNonBlocking);
    cudaEventCreateWithFlags(&evA, cudaEventDisableTiming);
    cudaEventCreateWithFlags(&evB, cudaEventDisableTiming);
    cudaEventCreateWithFlags(&evC, cudaEventDisableTiming);

    detect_kernel<<<1, 32, 0, s0>>>((const int*)ei);

    {
        TransBatch tb;
        const float* srcs[10] = {Wq, Wk, Wv, We, Wo_n, Wo_e, Wn1, Wn2, We1, We2};
        __half* dsts[10] = {WqkvT, WqkvT + 16384, WqkvT + 32768, WeT, WonT, WoeT,
                            Wn1T, Wn2T, We1T, We2T};
        int Rs[10] = {128, 128, 128, 128, 128, 128, 128, 256, 128, 256};
        int Cs[10] = {128, 128, 128, 128, 128, 128, 256, 128, 256, 128};
        for (int i = 0; i < 10; i++) {
            tb.src[i] = srcs[i]; tb.dst[i] = dsts[i]; tb.R[i] = Rs[i]; tb.C[i] = Cs[i];
        }
        transpose_all<<<dim3(8, 8, 10), dim3(32, 8), 0, s0>>>(tb);
    }

    ln2_kernel<<<(N + E + 7) / 8, blk, 0, s0>>>(node_feats, ln1n_g, ln1n_b, p_hln, N,
                                                edge_feats, ln1e_g, ln1e_b, p_eln, E);

    const int gN = (N + 127) / 128;
    const int gE = (E + 127) / 128;

    // ---- fork A: node qkv on s2 concurrent with edge dist/ep on s0 ----
    cudaEventRecord(evA, s0);
    cudaStreamWaitEvent(s2, evA, 0);

    mma_gemm<<<dim3(gN, 3), blk, GEMM_DYN, s2>>>(p_hln, 128, WqkvT, nullptr, p_qkv,
                                          N, 128, 384, nullptr, nullptr, 0,
                                          nullptr, nullptr, 0, nullptr, nullptr, nullptr);

    dist_kernel<<<(E + 255) / 256, blk, 0, s0>>>(coords, ei, p_dist, E);
    cudaMemsetAsync(p_wV, 0, (size_t)N * 128 * sizeof(float), s0);
    cudaMemsetAsync(p_z,  0, (size_t)N * 8 * sizeof(float), s0);
    mma_gemm<<<dim3(gE, 1), blk, GEMM_DYN, s0>>>(p_eln, 128, WeT, nullptr, p_ep,
                                          E, 128, 128, nullptr, nullptr, 0,
                                          p_dist, We + 128 * 128, 0, nullptr, nullptr, nullptr);

    cudaEventRecord(evB, s2);
    cudaStreamWaitEvent(s0, evB, 0);

    attn_edge_kernel<<<(E + 15) / 16, blk, 0, s0>>>(p_qkv, p_ep, p_eln, ei, p_wV, p_z, E);

    // ---- fork B: node path on s2 concurrent with edge path on s0 ----
    cudaEventRecord(evA, s0);
    cudaStreamWaitEvent(s2, evA, 0);

    hattn_kernel<<<(N * 128 + 255) / 256, blk, 0, s2>>>(p_wV, p_z, p_hln, N);
    mma_gemm<<<dim3(gN, 1), blk, GEMM_DYN, s2>>>(p_hln, 128, WonT, out_n, nullptr,
                                          N, 128, 128, bo_n, node_feats, 128,
                                          nullptr, nullptr, 0, ln2n_g, ln2n_b, p_hln);
    mma_gemm<<<dim3(gN, 2), blk, GEMM_DYN, s2>>>(p_hln, 128, Wn1T, nullptr, p_tn,
                                          N, 128, 256, nullptr, nullptr, 0,
                                          nullptr, nullptr, 1, nullptr, nullptr, nullptr);
    mma_gemm<<<dim3(gN, 1), blk, GEMM_DYN, s2>>>(p_tn, 256, Wn2T, out_n, nullptr,
                                          N, 256, 128, nullptr, out_n, 128,
                                          nullptr, nullptr, 0, nullptr, nullptr, nullptr);

    mma_gemm<<<dim3(gE, 1), blk, GEMM_DYN, s0>>>(p_eln, 128, WoeT, out_e, nullptr,
                                          E, 128, 128, bo_e, edge_feats, 128,
                                          nullptr, nullptr, 0, ln2e_g, ln2e_b, p_eln);
    mma_gemm<<<dim3(gE, 2), blk, GEMM_DYN, s0>>>(p_eln, 128, We1T, nullptr, p_t,
                                          E, 128, 256, nullptr, nullptr, 0,
                                          nullptr, nullptr, 1, nullptr, nullptr, nullptr);
    mma_gemm<<<dim3(gE, 1), blk, GEMM_DYN, s0>>>(p_t, 256, We2T, out_e, nullptr,
                                          E, 256, 128, nullptr, out_e, 128,
                                          nullptr, nullptr, 0, nullptr, nullptr, nullptr);

    cudaEventRecord(evC, s2);
    cudaStreamWaitEvent(s0, evC, 0);
}